// round 2
// baseline (speedup 1.0000x reference)
#include <cuda_runtime.h>
#include <math.h>

// ---------------- problem constants ----------------
#define BB    2
#define TT    2048
#define DIM   1024
#define NTOK  4096          // BB*TT
#define HEADS 16
#define HD    64
#define NEXP  8
#define HID   4096
#define MAXTOK 4096         // per-expert capacity (worst case)

// ---------------- device scratch (static, allowed) ----------------
__device__ float g_h   [NTOK * DIM];                 // ln1 out
__device__ float g_qkv [NTOK * 3 * DIM];             // qkv
__device__ float g_y   [NTOK * DIM];                 // attn out
__device__ float g_x1  [NTOK * DIM];                 // x + attn proj
__device__ float g_h2  [NTOK * DIM];                 // ln2 out
__device__ float g_hid [(size_t)NTOK * 2 * HID];     // gathered expert hidden pool (8192 rows)
__device__ float g_c   [2][NTOK * DIM];              // per-slot MoE contributions
__device__ int   g_cnt [NEXP];
__device__ int   g_base[NEXP];
__device__ int   g_tok [NEXP * MAXTOK];
__device__ float g_wt  [NEXP * MAXTOK];
__device__ int   g_slot[NEXP * MAXTOK];

// ---------------- tiny utility kernels ----------------
__global__ void zero_cnt_kernel() {
    if (threadIdx.x < NEXP) g_cnt[threadIdx.x] = 0;
}

__global__ void base_kernel() {
    if (threadIdx.x == 0) {
        int s = 0;
        for (int e = 0; e < NEXP; ++e) { g_base[e] = s; s += g_cnt[e]; }
    }
}

__global__ void final_kernel(float* __restrict__ out) {
    int i = blockIdx.x * 256 + threadIdx.x;
    out[i] = g_x1[i] + g_c[0][i] + g_c[1][i];
}

// ---------------- layernorm: one block (256 thr) per token ----------------
__global__ void ln_kernel(const float* __restrict__ in, const float* __restrict__ gam,
                          const float* __restrict__ bet, float* __restrict__ out) {
    __shared__ float sx[DIM];
    __shared__ float red[8];
    const int n = blockIdx.x, tid = threadIdx.x;
    const float* row = in + (size_t)n * DIM;

    float s = 0.f;
    // DIM/4 = 256 float4 -> one per thread
    {
        float4 x4 = ((const float4*)row)[tid];
        ((float4*)sx)[tid] = x4;
        s = x4.x + x4.y + x4.z + x4.w;
    }
    #pragma unroll
    for (int o = 16; o; o >>= 1) s += __shfl_xor_sync(~0u, s, o);
    if ((tid & 31) == 0) red[tid >> 5] = s;
    __syncthreads();
    float mu;
    {
        float t = (tid < 8) ? red[tid & 7] : 0.f; // all threads compute same
        // serialize tiny reduce: just have every thread sum 8 slots
        t = red[0] + red[1] + red[2] + red[3] + red[4] + red[5] + red[6] + red[7];
        mu = t * (1.0f / DIM);
    }
    float sq = 0.f;
    #pragma unroll
    for (int p = 0; p < 4; ++p) {
        float d = sx[tid + p * 256] - mu;
        sq += d * d;
    }
    #pragma unroll
    for (int o = 16; o; o >>= 1) sq += __shfl_xor_sync(~0u, sq, o);
    __syncthreads();
    if ((tid & 31) == 0) red[tid >> 5] = sq;
    __syncthreads();
    float var = (red[0] + red[1] + red[2] + red[3] + red[4] + red[5] + red[6] + red[7]) * (1.0f / DIM);
    float rs = rsqrtf(var + 1e-5f);
    float* orow = out + (size_t)n * DIM;
    #pragma unroll
    for (int p = 0; p < 4; ++p) {
        int d = tid + p * 256;
        orow[d] = (sx[d] - mu) * rs * gam[d] + bet[d];
    }
}

// ---------------- SGEMM: 128x128x8 tile, 8x8 micro-tile, 256 threads ----------------
// MODE 0: C = A @ B                               (qkv)
// MODE 1: C = aux + A @ B                         (proj + residual)
// MODE 2: per-expert gather-GEMM + bias + GELU    (moe up)
// MODE 3: per-expert GEMM + bias, scaled scatter  (moe down)
template <int MODE>
__global__ void __launch_bounds__(256)
gemm_kernel(const float* __restrict__ A, const float* __restrict__ Bm,
            float* __restrict__ C, int M, int N, int K,
            const float* __restrict__ aux) {
    const int e = (MODE >= 2) ? blockIdx.z : 0;
    int Mrows = M;
    const float* Bp = Bm;
    const float* Ap = A;
    const float* bias = aux;
    int pbase = 0;

    if (MODE == 2) {
        Mrows = g_cnt[e];
        if ((int)blockIdx.y * 128 >= Mrows) return;
        Bp = Bm + (size_t)e * K * N;
        bias = aux + (size_t)e * N;
        pbase = g_base[e];
    } else if (MODE == 3) {
        Mrows = g_cnt[e];
        if ((int)blockIdx.y * 128 >= Mrows) return;
        Ap = A + (size_t)g_base[e] * K;
        Bp = Bm + (size_t)e * K * N;
        bias = aux + (size_t)e * N;
    }

    __shared__ __align__(16) float As[8][128];
    __shared__ __align__(16) float Bs[8][128];

    float acc[8][8];
    #pragma unroll
    for (int i = 0; i < 8; ++i)
        #pragma unroll
        for (int j = 0; j < 8; ++j) acc[i][j] = 0.f;

    const int tid = threadIdx.x;
    const int tx = tid & 15, ty = tid >> 4;
    const int m0 = blockIdx.y * 128, n0 = blockIdx.x * 128;
    const int a_m = tid >> 1, a_k = (tid & 1) * 4;
    const int b_k = tid >> 5, b_n = (tid & 31) * 4;

    const float* a_src = nullptr;
    {
        int mm = m0 + a_m;
        if (mm < Mrows) {
            if (MODE == 2) a_src = A + (size_t)g_tok[e * MAXTOK + mm] * K;
            else           a_src = Ap + (size_t)mm * K;
        }
    }
    const float* b_src = Bp + (size_t)b_k * N + n0 + b_n;

    const int nk = K >> 3;
    for (int kt = 0; kt < nk; ++kt) {
        float4 av = make_float4(0.f, 0.f, 0.f, 0.f);
        if (a_src) av = *(const float4*)(a_src + kt * 8 + a_k);
        float4 bv = *(const float4*)(b_src + (size_t)kt * 8 * N);
        As[a_k + 0][a_m] = av.x;
        As[a_k + 1][a_m] = av.y;
        As[a_k + 2][a_m] = av.z;
        As[a_k + 3][a_m] = av.w;
        *(float4*)&Bs[b_k][b_n] = bv;
        __syncthreads();
        #pragma unroll
        for (int kk = 0; kk < 8; ++kk) {
            float4 a0 = *(const float4*)&As[kk][ty * 8];
            float4 a1 = *(const float4*)&As[kk][ty * 8 + 4];
            float4 c0 = *(const float4*)&Bs[kk][tx * 8];
            float4 c1 = *(const float4*)&Bs[kk][tx * 8 + 4];
            float ar[8] = {a0.x, a0.y, a0.z, a0.w, a1.x, a1.y, a1.z, a1.w};
            float br[8] = {c0.x, c0.y, c0.z, c0.w, c1.x, c1.y, c1.z, c1.w};
            #pragma unroll
            for (int i = 0; i < 8; ++i)
                #pragma unroll
                for (int j = 0; j < 8; ++j) acc[i][j] += ar[i] * br[j];
        }
        __syncthreads();
    }

    #pragma unroll
    for (int i = 0; i < 8; ++i) {
        const int m = m0 + ty * 8 + i;
        if (MODE >= 2 && m >= Mrows) continue;
        const int col0 = n0 + tx * 8;
        if (MODE == 0) {
            float* dst = C + (size_t)m * N + col0;
            #pragma unroll
            for (int j = 0; j < 8; ++j) dst[j] = acc[i][j];
        } else if (MODE == 1) {
            const float* r = aux + (size_t)m * N + col0;
            float* dst = C + (size_t)m * N + col0;
            #pragma unroll
            for (int j = 0; j < 8; ++j) dst[j] = r[j] + acc[i][j];
        } else if (MODE == 2) {
            float* dst = C + (size_t)(pbase + m) * N + col0;
            #pragma unroll
            for (int j = 0; j < 8; ++j) {
                float v = acc[i][j] + bias[col0 + j];
                dst[j] = 0.5f * v * (1.f + erff(v * 0.70710678118654752f));
            }
        } else { // MODE 3
            const int t = g_tok[e * MAXTOK + m];
            const float w = g_wt[e * MAXTOK + m];
            const int s = g_slot[e * MAXTOK + m];
            float* dst = &g_c[s][(size_t)t * DIM + col0];
            #pragma unroll
            for (int j = 0; j < 8; ++j) dst[j] = w * (acc[i][j] + bias[col0 + j]);
        }
    }
}

// ---------------- flash attention: 64 q rows x 64 kv per tile ----------------
__global__ void __launch_bounds__(256)
attn_kernel(const float* __restrict__ qkv, float* __restrict__ y) {
    __shared__ __align__(16) float sQ[64][64];   // [d][r], pre-scaled by 1/8
    __shared__ __align__(16) float sKP[64][64];  // [d][j] as K, then [j][r] as P
    __shared__ __align__(16) float sV[64][64];   // [j][d]

    const int qt = blockIdx.x, bh = blockIdx.y;
    const int b = bh >> 4, h = bh & 15;
    const int tid = threadIdx.x, tx = tid & 15, ty = tid >> 4;
    const int qbase = qt * 64;

    // load Q transposed, pre-scaled
    #pragma unroll
    for (int p = 0; p < 4; ++p) {
        int v = tid + p * 256;
        int r = v >> 4, d4 = (v & 15) * 4;
        float4 q4 = *(const float4*)(qkv + (size_t)(b * TT + qbase + r) * (3 * DIM) + h * HD + d4);
        sQ[d4 + 0][r] = q4.x * 0.125f;
        sQ[d4 + 1][r] = q4.y * 0.125f;
        sQ[d4 + 2][r] = q4.z * 0.125f;
        sQ[d4 + 3][r] = q4.w * 0.125f;
    }

    float m_i[4], l_i[4], O[4][4];
    #pragma unroll
    for (int i = 0; i < 4; ++i) {
        m_i[i] = -1e30f; l_i[i] = 0.f;
        #pragma unroll
        for (int j = 0; j < 4; ++j) O[i][j] = 0.f;
    }

    for (int kb = 0; kb <= qt; ++kb) {
        const int kbase = kb * 64;
        __syncthreads();  // previous iteration fully consumed sKP / sV
        #pragma unroll
        for (int p = 0; p < 4; ++p) {
            int v = tid + p * 256;
            int j = v >> 4, d4 = (v & 15) * 4;
            size_t base = (size_t)(b * TT + kbase + j) * (3 * DIM) + h * HD + d4;
            float4 k4 = *(const float4*)(qkv + base + DIM);
            sKP[d4 + 0][j] = k4.x;
            sKP[d4 + 1][j] = k4.y;
            sKP[d4 + 2][j] = k4.z;
            sKP[d4 + 3][j] = k4.w;
            float4 v4 = *(const float4*)(qkv + base + 2 * DIM);
            *(float4*)&sV[j][d4] = v4;
        }
        __syncthreads();

        // S = Q K^T (tile) in registers
        float s[4][4];
        #pragma unroll
        for (int i = 0; i < 4; ++i)
            #pragma unroll
            for (int j = 0; j < 4; ++j) s[i][j] = 0.f;
        #pragma unroll 4
        for (int d = 0; d < 64; ++d) {
            float4 a  = *(const float4*)&sQ[d][ty * 4];
            float4 bk = *(const float4*)&sKP[d][tx * 4];
            float ar[4] = {a.x, a.y, a.z, a.w};
            float br[4] = {bk.x, bk.y, bk.z, bk.w};
            #pragma unroll
            for (int i = 0; i < 4; ++i)
                #pragma unroll
                for (int j = 0; j < 4; ++j) s[i][j] += ar[i] * br[j];
        }
        if (kb == qt) {
            #pragma unroll
            for (int i = 0; i < 4; ++i)
                #pragma unroll
                for (int j = 0; j < 4; ++j)
                    if (tx * 4 + j > ty * 4 + i) s[i][j] = -1e30f;
        }

        float corr[4], p_[4][4];
        #pragma unroll
        for (int i = 0; i < 4; ++i) {
            float mt = fmaxf(fmaxf(s[i][0], s[i][1]), fmaxf(s[i][2], s[i][3]));
            #pragma unroll
            for (int o = 8; o; o >>= 1) mt = fmaxf(mt, __shfl_xor_sync(~0u, mt, o, 16));
            float mn = fmaxf(m_i[i], mt);
            corr[i] = __expf(m_i[i] - mn);
            m_i[i] = mn;
            float rsum = 0.f;
            #pragma unroll
            for (int j = 0; j < 4; ++j) {
                p_[i][j] = __expf(s[i][j] - mn);
                rsum += p_[i][j];
            }
            #pragma unroll
            for (int o = 8; o; o >>= 1) rsum += __shfl_xor_sync(~0u, rsum, o, 16);
            l_i[i] = l_i[i] * corr[i] + rsum;
        }

        __syncthreads();  // done reading sKP as K
        #pragma unroll
        for (int i = 0; i < 4; ++i)
            #pragma unroll
            for (int j = 0; j < 4; ++j)
                sKP[tx * 4 + j][ty * 4 + i] = p_[i][j];   // P^T: [j][r]
        __syncthreads();

        #pragma unroll
        for (int i = 0; i < 4; ++i)
            #pragma unroll
            for (int j = 0; j < 4; ++j) O[i][j] *= corr[i];
        #pragma unroll 4
        for (int jj = 0; jj < 64; ++jj) {
            float4 a  = *(const float4*)&sKP[jj][ty * 4];
            float4 vv = *(const float4*)&sV[jj][tx * 4];
            float ar[4] = {a.x, a.y, a.z, a.w};
            float br[4] = {vv.x, vv.y, vv.z, vv.w};
            #pragma unroll
            for (int i = 0; i < 4; ++i)
                #pragma unroll
                for (int j = 0; j < 4; ++j) O[i][j] += ar[i] * br[j];
        }
    }

    #pragma unroll
    for (int i = 0; i < 4; ++i) {
        float inv = 1.f / l_i[i];
        float4 o4 = make_float4(O[i][0] * inv, O[i][1] * inv, O[i][2] * inv, O[i][3] * inv);
        *(float4*)(y + (size_t)(b * TT + qbase + ty * 4 + i) * DIM + h * HD + tx * 4) = o4;
    }
}

// ---------------- router: one block (128 thr) per token ----------------
__global__ void router_kernel(const float* __restrict__ h2, const float* __restrict__ wr) {
    const int n = blockIdx.x, tid = threadIdx.x;
    float acc[NEXP];
    #pragma unroll
    for (int e = 0; e < NEXP; ++e) acc[e] = 0.f;
    const float* row = h2 + (size_t)n * DIM;
    for (int d = tid; d < DIM; d += 128) {
        float hv = row[d];
        #pragma unroll
        for (int e = 0; e < NEXP; ++e) acc[e] += hv * wr[d * NEXP + e];
    }
    __shared__ float sm[4][NEXP];
    #pragma unroll
    for (int e = 0; e < NEXP; ++e) {
        float v = acc[e];
        #pragma unroll
        for (int o = 16; o; o >>= 1) v += __shfl_xor_sync(~0u, v, o);
        if ((tid & 31) == 0) sm[tid >> 5][e] = v;
    }
    __syncthreads();
    if (tid == 0) {
        float lg[NEXP];
        #pragma unroll
        for (int e = 0; e < NEXP; ++e) lg[e] = sm[0][e] + sm[1][e] + sm[2][e] + sm[3][e];
        int e0 = 0;
        #pragma unroll
        for (int e = 1; e < NEXP; ++e) if (lg[e] > lg[e0]) e0 = e;
        int e1 = -1;
        #pragma unroll
        for (int e = 0; e < NEXP; ++e)
            if (e != e0 && (e1 < 0 || lg[e] > lg[e1])) e1 = e;
        float w0 = 1.f / (1.f + __expf(lg[e1] - lg[e0]));
        float w1 = 1.f - w0;
        int p0 = atomicAdd(&g_cnt[e0], 1);
        g_tok[e0 * MAXTOK + p0] = n; g_wt[e0 * MAXTOK + p0] = w0; g_slot[e0 * MAXTOK + p0] = 0;
        int p1 = atomicAdd(&g_cnt[e1], 1);
        g_tok[e1 * MAXTOK + p1] = n; g_wt[e1 * MAXTOK + p1] = w1; g_slot[e1 * MAXTOK + p1] = 1;
    }
}

// ---------------- launch ----------------
extern "C" void kernel_launch(void* const* d_in, const int* in_sizes, int n_in,
                              void* d_out, int out_size) {
    const float* x        = (const float*)d_in[0];
    const float* ln1_g    = (const float*)d_in[1];
    const float* ln1_b    = (const float*)d_in[2];
    const float* w_attn   = (const float*)d_in[3];
    const float* w_proj   = (const float*)d_in[4];
    const float* ln2_g    = (const float*)d_in[5];
    const float* ln2_b    = (const float*)d_in[6];
    const float* w_router = (const float*)d_in[7];
    const float* w1       = (const float*)d_in[8];
    const float* b1       = (const float*)d_in[9];
    const float* w2       = (const float*)d_in[10];
    const float* b2       = (const float*)d_in[11];
    float* out = (float*)d_out;

    float *p_h, *p_qkv, *p_y, *p_x1, *p_h2, *p_hid;
    cudaGetSymbolAddress((void**)&p_h,   g_h);
    cudaGetSymbolAddress((void**)&p_qkv, g_qkv);
    cudaGetSymbolAddress((void**)&p_y,   g_y);
    cudaGetSymbolAddress((void**)&p_x1,  g_x1);
    cudaGetSymbolAddress((void**)&p_h2,  g_h2);
    cudaGetSymbolAddress((void**)&p_hid, g_hid);

    zero_cnt_kernel<<<1, 32>>>();
    ln_kernel<<<NTOK, 256>>>(x, ln1_g, ln1_b, p_h);

    // qkv = h @ w_attn : [4096,1024]x[1024,3072]
    gemm_kernel<0><<<dim3(3 * DIM / 128, NTOK / 128), 256>>>(p_h, w_attn, p_qkv,
                                                             NTOK, 3 * DIM, DIM, nullptr);
    // attention
    attn_kernel<<<dim3(TT / 64, BB * HEADS), 256>>>(p_qkv, p_y);

    // x1 = x + y @ w_proj
    gemm_kernel<1><<<dim3(DIM / 128, NTOK / 128), 256>>>(p_y, w_proj, p_x1,
                                                         NTOK, DIM, DIM, x);
    // ln2
    ln_kernel<<<NTOK, 256>>>(p_x1, ln2_g, ln2_b, p_h2);

    // routing
    router_kernel<<<NTOK, 128>>>(p_h2, w_router);
    base_kernel<<<1, 32>>>();

    // MoE up: gathered rows of h2 -> gelu(h2 @ w1[e] + b1[e])
    gemm_kernel<2><<<dim3(HID / 128, NTOK / 128, NEXP), 256>>>(p_h2, w1, p_hid,
                                                               NTOK, HID, DIM, b1);
    // MoE down: hid @ w2[e] + b2[e], scaled scatter into g_c[slot]
    gemm_kernel<3><<<dim3(DIM / 128, NTOK / 128, NEXP), 256>>>(p_hid, w2, nullptr,
                                                               NTOK, DIM, HID, b2);
    // out = x1 + c0 + c1
    final_kernel<<<NTOK * DIM / 256, 256>>>(out);
}

// round 4
// speedup vs baseline: 1.3732x; 1.3732x over previous
#include <cuda_runtime.h>
#include <cuda_bf16.h>
#include <math.h>
#include <stdint.h>

#define BB 2
#define TT 2048
#define DIM 1024
#define NTOK 4096
#define NEXP 8
#define HID 4096
#define MAXTOK 4096
typedef __nv_bfloat16 bf16;

// ---------- scratch ----------
__device__ bf16 g_h_hi[NTOK*DIM], g_h_lo[NTOK*DIM];
__device__ float g_qkv[(size_t)NTOK*3*DIM];
__device__ bf16 g_y_hi[NTOK*DIM], g_y_lo[NTOK*DIM];
__device__ float g_x1[NTOK*DIM], g_h2f[NTOK*DIM];
__device__ bf16 g_h2_hi[NTOK*DIM], g_h2_lo[NTOK*DIM];
__device__ bf16 g_pool_hi[(size_t)2*NTOK*HID], g_pool_lo[(size_t)2*NTOK*HID];
__device__ float g_c0[NTOK*DIM], g_c1[NTOK*DIM];
__device__ int g_cnt[NEXP], g_basei[NEXP], g_tok[NEXP*MAXTOK], g_slot[NEXP*MAXTOK];
__device__ float g_wt[NEXP*MAXTOK];
__device__ bf16 g_waT_hi[(size_t)3*DIM*DIM], g_waT_lo[(size_t)3*DIM*DIM];
__device__ bf16 g_wpT_hi[(size_t)DIM*DIM],   g_wpT_lo[(size_t)DIM*DIM];
__device__ bf16 g_w1T_hi[(size_t)NEXP*HID*DIM], g_w1T_lo[(size_t)NEXP*HID*DIM];
__device__ bf16 g_w2T_hi[(size_t)NEXP*DIM*HID], g_w2T_lo[(size_t)NEXP*DIM*HID];

// ---------- ptx helpers ----------
__device__ __forceinline__ uint32_t s2u(const void* p){
    uint32_t a; asm("{ .reg .u64 t; cvta.to.shared.u64 t, %1; cvt.u32.u64 %0, t; }":"=r"(a):"l"(p)); return a;
}
__device__ __forceinline__ uint32_t swz(uint32_t o){ return o ^ ((o>>3)&0x70); }
__device__ __forceinline__ void cp16(uint32_t d, const bf16* s, bool v){
    asm volatile("cp.async.cg.shared.global [%0], [%1], 16, %2;"
        ::"r"(d),"l"(__cvta_generic_to_global(s)),"r"(v?16:0));
}
__device__ __forceinline__ void ldx4(uint32_t* r, uint32_t a){
    asm volatile("ldmatrix.sync.aligned.m8n8.x4.shared.b16 {%0,%1,%2,%3},[%4];"
        :"=r"(r[0]),"=r"(r[1]),"=r"(r[2]),"=r"(r[3]):"r"(a));
}
__device__ __forceinline__ void mma16816(float* d, const uint32_t* a, const uint32_t* b){
    asm volatile("mma.sync.aligned.m16n8k16.row.col.f32.bf16.bf16.f32 "
        "{%0,%1,%2,%3},{%4,%5,%6,%7},{%8,%9},{%0,%1,%2,%3};"
        : "+f"(d[0]),"+f"(d[1]),"+f"(d[2]),"+f"(d[3])
        : "r"(a[0]),"r"(a[1]),"r"(a[2]),"r"(a[3]),"r"(b[0]),"r"(b[1]));
}

// ---------- small kernels ----------
__global__ void zero_cnt_kernel(){ if(threadIdx.x<NEXP) g_cnt[threadIdx.x]=0; }
__global__ void base_kernel(){
    if(threadIdx.x==0){ int s=0; for(int e=0;e<NEXP;++e){ g_basei[e]=s; s+=g_cnt[e]; } }
}
__global__ void final_kernel(float* __restrict__ out){
    int i = blockIdx.x*256 + threadIdx.x;
    out[i] = g_x1[i] + g_c0[i] + g_c1[i];
}

// ---------- layernorm ----------
template<int WHICH>
__global__ void ln_kernel(const float* __restrict__ in, const float* __restrict__ gam,
                          const float* __restrict__ bet){
    __shared__ float sx[DIM]; __shared__ float red[8];
    const int n=blockIdx.x, tid=threadIdx.x;
    const float* row = (WHICH==0 ? in : g_x1) + (size_t)n*DIM;
    float4 x4 = ((const float4*)row)[tid];
    ((float4*)sx)[tid] = x4;
    float s = x4.x+x4.y+x4.z+x4.w;
    #pragma unroll
    for(int o=16;o;o>>=1) s += __shfl_xor_sync(~0u,s,o);
    if((tid&31)==0) red[tid>>5]=s;
    __syncthreads();
    float mu = (red[0]+red[1]+red[2]+red[3]+red[4]+red[5]+red[6]+red[7])*(1.f/DIM);
    float sq=0.f;
    #pragma unroll
    for(int p=0;p<4;++p){ float d=sx[tid+p*256]-mu; sq+=d*d; }
    #pragma unroll
    for(int o=16;o;o>>=1) sq += __shfl_xor_sync(~0u,sq,o);
    __syncthreads();
    if((tid&31)==0) red[tid>>5]=sq;
    __syncthreads();
    float var=(red[0]+red[1]+red[2]+red[3]+red[4]+red[5]+red[6]+red[7])*(1.f/DIM);
    float rs = rsqrtf(var+1e-5f);
    #pragma unroll
    for(int p=0;p<4;++p){
        int d=tid+p*256;
        float v = (sx[d]-mu)*rs*gam[d]+bet[d];
        size_t o=(size_t)n*DIM+d;
        bf16 h = __float2bfloat16(v);
        bf16 l = __float2bfloat16(v - __bfloat162float(h));
        if(WHICH==0){ g_h_hi[o]=h; g_h_lo[o]=l; }
        else { g_h2f[o]=v; g_h2_hi[o]=h; g_h2_lo[o]=l; }
    }
}

// ---------- weight transpose + split ----------
template<int WHICH>
__global__ void transpose_split(const float* __restrict__ src){
    constexpr int Kd = (WHICH==3)?HID:DIM;
    constexpr int Nd = (WHICH==0)?3*DIM:((WHICH==2)?HID:DIM);
    bf16 *dhi, *dlo;
    if(WHICH==0){dhi=g_waT_hi;dlo=g_waT_lo;}
    else if(WHICH==1){dhi=g_wpT_hi;dlo=g_wpT_lo;}
    else if(WHICH==2){dhi=g_w1T_hi;dlo=g_w1T_lo;}
    else {dhi=g_w2T_hi;dlo=g_w2T_lo;}
    const int e=blockIdx.z;
    src += (size_t)e*Kd*Nd; dhi += (size_t)e*(size_t)Nd*Kd; dlo += (size_t)e*(size_t)Nd*Kd;
    __shared__ float t[32][33];
    const int n0=blockIdx.x*32, k0=blockIdx.y*32;
    for(int i=threadIdx.y;i<32;i+=8)
        t[i][threadIdx.x] = src[(size_t)(k0+i)*Nd + n0 + threadIdx.x];
    __syncthreads();
    for(int i=threadIdx.y;i<32;i+=8){
        float v = t[threadIdx.x][i];
        size_t o = (size_t)(n0+i)*Kd + k0 + threadIdx.x;
        bf16 h = __float2bfloat16(v);
        dhi[o]=h; dlo[o]=__float2bfloat16(v-__bfloat162float(h));
    }
}

// ---------- mma.sync split-bf16 GEMM: block 128x128, K-step 64, dbl-buffered ----------
// MODE 0 qkv, 1 proj(+x), 2 moe-up(gather,gelu->pool), 3 moe-dn(pool,scatter)
template<int MODE, int N, int K>
__global__ void __launch_bounds__(256,1) tgemm(const float* __restrict__ aux){
    constexpr int NKT = K/64;
    const int e = (MODE>=2)? blockIdx.z : 0;
    int Mrows = NTOK, pbase = 0;
    if(MODE>=2){
        Mrows = g_cnt[e]; pbase = g_basei[e];
        if((int)blockIdx.y*128 >= Mrows) return;
    }
    extern __shared__ char smem[];
    const uint32_t sb = s2u(smem);
    const int tid = threadIdx.x, lane = tid&31, wid = tid>>5;
    const int wm = wid>>2, wn = wid&3;            // warps 2x4, warp tile 64x32
    const int m0 = blockIdx.y*128, n0 = blockIdx.x*128;

    const bf16 *Ahi,*Alo,*Bhi,*Blo;
    if(MODE==0){ Ahi=g_h_hi; Alo=g_h_lo; Bhi=g_waT_hi; Blo=g_waT_lo; }
    else if(MODE==1){ Ahi=g_y_hi; Alo=g_y_lo; Bhi=g_wpT_hi; Blo=g_wpT_lo; }
    else if(MODE==2){ Ahi=g_h2_hi; Alo=g_h2_lo;
        Bhi=g_w1T_hi+(size_t)e*HID*DIM; Blo=g_w1T_lo+(size_t)e*HID*DIM; }
    else { Ahi=g_pool_hi; Alo=g_pool_lo;
        Bhi=g_w2T_hi+(size_t)e*DIM*HID; Blo=g_w2T_lo+(size_t)e*DIM*HID; }

    // cp.async plan: 4 chunks/thread per 16KB region (128 rows x 128B)
    const bf16 *pah[4],*pal[4],*pbh[4],*pbl[4]; uint32_t doff[4]; bool av[4];
    #pragma unroll
    for(int i=0;i<4;++i){
        int idx=tid+i*256, r=idx>>3, c=idx&7;
        doff[i]=swz((uint32_t)(r*128+c*16));
        int gm=m0+r; bool v=true; long rg=gm;
        if(MODE==2){ v = gm<Mrows; rg = v ? g_tok[e*MAXTOK+gm] : 0; }
        if(MODE==3){ v = gm<Mrows; rg = (long)pbase + (v?gm:0); }
        pah[i]=Ahi+(size_t)rg*K+c*8; pal[i]=Alo+(size_t)rg*K+c*8; av[i]=v;
        pbh[i]=Bhi+(size_t)(n0+r)*K+c*8; pbl[i]=Blo+(size_t)(n0+r)*K+c*8;
    }

    float acc[4][4][4];
    #pragma unroll
    for(int a=0;a<4;++a)
        #pragma unroll
        for(int b=0;b<4;++b)
            #pragma unroll
            for(int c=0;c<4;++c) acc[a][b][c]=0.f;

    // ldmatrix offsets (within 16KB region), per k16 step
    const int arow = wm*64 + (lane&15), achk = lane>>4;        // + mi*16
    const int brow = wn*32 + ((lane>>4)&1)*8 + (lane&7), bchk = (lane>>3)&1;  // + np*16

    auto issue = [&](int kt){
        const uint32_t st = sb + (kt&1)*65536;
        const int ko = kt*64;
        #pragma unroll
        for(int i=0;i<4;++i){
            cp16(st+doff[i],        pah[i]+ko, av[i]);
            cp16(st+16384+doff[i],  pal[i]+ko, av[i]);
            cp16(st+32768+doff[i],  pbh[i]+ko, true);
            cp16(st+49152+doff[i],  pbl[i]+ko, true);
        }
        asm volatile("cp.async.commit_group;":::"memory");
    };

    issue(0);
    for(int kt=0; kt<NKT; ++kt){
        if(kt+1<NKT){ issue(kt+1); asm volatile("cp.async.wait_group 1;":::"memory"); }
        else        { asm volatile("cp.async.wait_group 0;":::"memory"); }
        __syncthreads();
        const uint32_t st = sb + (kt&1)*65536;
        #pragma unroll
        for(int k16=0;k16<4;++k16){
            uint32_t ah[4][4], al[4][4], bh[4][2], bl[4][2];
            #pragma unroll
            for(int mi=0;mi<4;++mi){
                uint32_t off = (uint32_t)((arow+mi*16)*128 + k16*32 + achk*16);
                ldx4(ah[mi], st + swz(off));
                ldx4(al[mi], st + 16384 + swz(off));
            }
            #pragma unroll
            for(int np=0;np<2;++np){
                uint32_t off = (uint32_t)((brow+np*16)*128 + k16*32 + bchk*16);
                uint32_t r[4];
                ldx4(r, st + 32768 + swz(off));
                bh[np*2][0]=r[0]; bh[np*2][1]=r[1]; bh[np*2+1][0]=r[2]; bh[np*2+1][1]=r[3];
                ldx4(r, st + 49152 + swz(off));
                bl[np*2][0]=r[0]; bl[np*2][1]=r[1]; bl[np*2+1][0]=r[2]; bl[np*2+1][1]=r[3];
            }
            #pragma unroll
            for(int mi=0;mi<4;++mi)
                #pragma unroll
                for(int ni=0;ni<4;++ni){
                    mma16816(acc[mi][ni], ah[mi], bh[ni]);
                    mma16816(acc[mi][ni], ah[mi], bl[ni]);
                    mma16816(acc[mi][ni], al[mi], bh[ni]);
                }
        }
        __syncthreads();
    }

    // epilogue
    const int r0 = lane>>2, c2 = (lane&3)*2;
    const float* bias = (MODE>=2)? (aux+(size_t)e*N) : aux;
    #pragma unroll
    for(int mi=0;mi<4;++mi){
        #pragma unroll
        for(int half=0; half<2; ++half){
            const int m = m0 + wm*64 + mi*16 + r0 + half*8;
            if(MODE>=2 && m>=Mrows) continue;
            int tok=0, slot=0; float wgt=0.f;
            if(MODE==3){ int ix=e*MAXTOK+m; tok=g_tok[ix]; wgt=g_wt[ix]; slot=g_slot[ix]; }
            #pragma unroll
            for(int ni=0;ni<4;++ni){
                const int col = n0 + wn*32 + ni*8 + c2;
                float d0 = acc[mi][ni][half*2], d1 = acc[mi][ni][half*2+1];
                if(MODE==0){
                    float* dst=g_qkv+(size_t)m*N+col;
                    dst[0]=d0; dst[1]=d1;
                } else if(MODE==1){
                    const float* rx=aux+(size_t)m*N+col;
                    float* dst=g_x1+(size_t)m*N+col;
                    dst[0]=rx[0]+d0; dst[1]=rx[1]+d1;
                } else if(MODE==2){
                    size_t prow=(size_t)(pbase+m);
                    float v0=d0+bias[col], v1=d1+bias[col+1];
                    float gg0=0.5f*v0*(1.f+erff(v0*0.70710678f));
                    float gg1=0.5f*v1*(1.f+erff(v1*0.70710678f));
                    bf16 h0=__float2bfloat16(gg0), h1=__float2bfloat16(gg1);
                    g_pool_hi[prow*HID+col]=h0;   g_pool_hi[prow*HID+col+1]=h1;
                    g_pool_lo[prow*HID+col]=__float2bfloat16(gg0-__bfloat162float(h0));
                    g_pool_lo[prow*HID+col+1]=__float2bfloat16(gg1-__bfloat162float(h1));
                } else {
                    float* dst=(slot?g_c1:g_c0)+(size_t)tok*DIM+col;
                    dst[0]=wgt*(d0+bias[col]); dst[1]=wgt*(d1+bias[col+1]);
                }
            }
        }
    }
}

// ---------- flash attention (fp32), writes y hi/lo ----------
__global__ void __launch_bounds__(256)
attn_kernel(){
    __shared__ __align__(16) float sQ[64][64];
    __shared__ __align__(16) float sKP[64][64];
    __shared__ __align__(16) float sV[64][64];
    const float* qkv = g_qkv;
    const int qt=blockIdx.x, bh=blockIdx.y;
    const int b=bh>>4, h=bh&15;
    const int tid=threadIdx.x, tx=tid&15, ty=tid>>4;
    const int qbase=qt*64;
    #pragma unroll
    for(int p=0;p<4;++p){
        int v=tid+p*256, r=v>>4, d4=(v&15)*4;
        float4 q4=*(const float4*)(qkv+(size_t)(b*TT+qbase+r)*(3*DIM)+h*64+d4);
        sQ[d4+0][r]=q4.x*0.125f; sQ[d4+1][r]=q4.y*0.125f;
        sQ[d4+2][r]=q4.z*0.125f; sQ[d4+3][r]=q4.w*0.125f;
    }
    float m_i[4], l_i[4], O[4][4];
    #pragma unroll
    for(int i=0;i<4;++i){ m_i[i]=-1e30f; l_i[i]=0.f;
        #pragma unroll
        for(int j=0;j<4;++j) O[i][j]=0.f; }
    for(int kb=0;kb<=qt;++kb){
        const int kbase=kb*64;
        __syncthreads();
        #pragma unroll
        for(int p=0;p<4;++p){
            int v=tid+p*256, j=v>>4, d4=(v&15)*4;
            size_t base=(size_t)(b*TT+kbase+j)*(3*DIM)+h*64+d4;
            float4 k4=*(const float4*)(qkv+base+DIM);
            sKP[d4+0][j]=k4.x; sKP[d4+1][j]=k4.y; sKP[d4+2][j]=k4.z; sKP[d4+3][j]=k4.w;
            *(float4*)&sV[j][d4]=*(const float4*)(qkv+base+2*DIM);
        }
        __syncthreads();
        float s[4][4];
        #pragma unroll
        for(int i=0;i<4;++i)
            #pragma unroll
            for(int j=0;j<4;++j) s[i][j]=0.f;
        #pragma unroll 4
        for(int d=0;d<64;++d){
            float4 a=*(const float4*)&sQ[d][ty*4];
            float4 bk=*(const float4*)&sKP[d][tx*4];
            float ar[4]={a.x,a.y,a.z,a.w}, br[4]={bk.x,bk.y,bk.z,bk.w};
            #pragma unroll
            for(int i=0;i<4;++i)
                #pragma unroll
                for(int j=0;j<4;++j) s[i][j]+=ar[i]*br[j];
        }
        if(kb==qt){
            #pragma unroll
            for(int i=0;i<4;++i)
                #pragma unroll
                for(int j=0;j<4;++j)
                    if(tx*4+j>ty*4+i) s[i][j]=-1e30f;
        }
        float corr[4], p_[4][4];
        #pragma unroll
        for(int i=0;i<4;++i){
            float mt=fmaxf(fmaxf(s[i][0],s[i][1]),fmaxf(s[i][2],s[i][3]));
            #pragma unroll
            for(int o=8;o;o>>=1) mt=fmaxf(mt,__shfl_xor_sync(~0u,mt,o,16));
            float mn=fmaxf(m_i[i],mt);
            corr[i]=__expf(m_i[i]-mn); m_i[i]=mn;
            float rs=0.f;
            #pragma unroll
            for(int j=0;j<4;++j){ p_[i][j]=__expf(s[i][j]-mn); rs+=p_[i][j]; }
            #pragma unroll
            for(int o=8;o;o>>=1) rs+=__shfl_xor_sync(~0u,rs,o,16);
            l_i[i]=l_i[i]*corr[i]+rs;
        }
        __syncthreads();
        #pragma unroll
        for(int i=0;i<4;++i)
            #pragma unroll
            for(int j=0;j<4;++j) sKP[tx*4+j][ty*4+i]=p_[i][j];
        __syncthreads();
        #pragma unroll
        for(int i=0;i<4;++i)
            #pragma unroll
            for(int j=0;j<4;++j) O[i][j]*=corr[i];
        #pragma unroll 4
        for(int jj=0;jj<64;++jj){
            float4 a=*(const float4*)&sKP[jj][ty*4];
            float4 vv=*(const float4*)&sV[jj][tx*4];
            float ar[4]={a.x,a.y,a.z,a.w}, br[4]={vv.x,vv.y,vv.z,vv.w};
            #pragma unroll
            for(int i=0;i<4;++i)
                #pragma unroll
                for(int j=0;j<4;++j) O[i][j]+=ar[i]*br[j];
        }
    }
    #pragma unroll
    for(int i=0;i<4;++i){
        float inv=1.f/l_i[i];
        size_t o=(size_t)(b*TT+qbase+ty*4+i)*DIM+h*64+tx*4;
        #pragma unroll
        for(int j=0;j<4;++j){
            float v=O[i][j]*inv;
            bf16 hh=__float2bfloat16(v);
            g_y_hi[o+j]=hh; g_y_lo[o+j]=__float2bfloat16(v-__bfloat162float(hh));
        }
    }
}

// ---------- router ----------
__global__ void router_kernel(const float* __restrict__ wr){
    const int n=blockIdx.x, tid=threadIdx.x;
    float acc[NEXP];
    #pragma unroll
    for(int e=0;e<NEXP;++e) acc[e]=0.f;
    const float* row=g_h2f+(size_t)n*DIM;
    for(int d=tid;d<DIM;d+=128){
        float hv=row[d];
        #pragma unroll
        for(int e=0;e<NEXP;++e) acc[e]+=hv*wr[d*NEXP+e];
    }
    __shared__ float sm[4][NEXP];
    #pragma unroll
    for(int e=0;e<NEXP;++e){
        float v=acc[e];
        #pragma unroll
        for(int o=16;o;o>>=1) v+=__shfl_xor_sync(~0u,v,o);
        if((tid&31)==0) sm[tid>>5][e]=v;
    }
    __syncthreads();
    if(tid==0){
        float lg[NEXP];
        #pragma unroll
        for(int e=0;e<NEXP;++e) lg[e]=sm[0][e]+sm[1][e]+sm[2][e]+sm[3][e];
        int e0=0;
        #pragma unroll
        for(int e=1;e<NEXP;++e) if(lg[e]>lg[e0]) e0=e;
        int e1=-1;
        #pragma unroll
        for(int e=0;e<NEXP;++e) if(e!=e0 && (e1<0||lg[e]>lg[e1])) e1=e;
        float w0=1.f/(1.f+__expf(lg[e1]-lg[e0])), w1=1.f-w0;
        int p0=atomicAdd(&g_cnt[e0],1);
        g_tok[e0*MAXTOK+p0]=n; g_wt[e0*MAXTOK+p0]=w0; g_slot[e0*MAXTOK+p0]=0;
        int p1=atomicAdd(&g_cnt[e1],1);
        g_tok[e1*MAXTOK+p1]=n; g_wt[e1*MAXTOK+p1]=w1; g_slot[e1*MAXTOK+p1]=1;
    }
}

// ---------- launch ----------
extern "C" void kernel_launch(void* const* d_in, const int* in_sizes, int n_in,
                              void* d_out, int out_size){
    const float* x      =(const float*)d_in[0];
    const float* ln1_g  =(const float*)d_in[1];
    const float* ln1_b  =(const float*)d_in[2];
    const float* w_attn =(const float*)d_in[3];
    const float* w_proj =(const float*)d_in[4];
    const float* ln2_g  =(const float*)d_in[5];
    const float* ln2_b  =(const float*)d_in[6];
    const float* w_rtr  =(const float*)d_in[7];
    const float* w1     =(const float*)d_in[8];
    const float* b1     =(const float*)d_in[9];
    const float* w2     =(const float*)d_in[10];
    const float* b2     =(const float*)d_in[11];
    float* out=(float*)d_out;

    const int SM = 131072;
    cudaFuncSetAttribute(tgemm<0,3*DIM,DIM>, cudaFuncAttributeMaxDynamicSharedMemorySize, SM);
    cudaFuncSetAttribute(tgemm<1,DIM,DIM>,   cudaFuncAttributeMaxDynamicSharedMemorySize, SM);
    cudaFuncSetAttribute(tgemm<2,HID,DIM>,   cudaFuncAttributeMaxDynamicSharedMemorySize, SM);
    cudaFuncSetAttribute(tgemm<3,DIM,HID>,   cudaFuncAttributeMaxDynamicSharedMemorySize, SM);

    zero_cnt_kernel<<<1,32>>>();
    transpose_split<0><<<dim3(96,32,1), dim3(32,8)>>>(w_attn);
    transpose_split<1><<<dim3(32,32,1), dim3(32,8)>>>(w_proj);
    transpose_split<2><<<dim3(128,32,NEXP), dim3(32,8)>>>(w1);
    transpose_split<3><<<dim3(32,128,NEXP), dim3(32,8)>>>(w2);

    ln_kernel<0><<<NTOK,256>>>(x, ln1_g, ln1_b);
    tgemm<0,3*DIM,DIM><<<dim3(24,32,1),256,SM>>>(nullptr);
    attn_kernel<<<dim3(TT/64,BB*16),256>>>();
    tgemm<1,DIM,DIM><<<dim3(8,32,1),256,SM>>>(x);
    ln_kernel<1><<<NTOK,256>>>(nullptr, ln2_g, ln2_b);
    router_kernel<<<NTOK,128>>>(w_rtr);
    base_kernel<<<1,32>>>();
    tgemm<2,HID,DIM><<<dim3(32,32,NEXP),256,SM>>>(b1);
    tgemm<3,DIM,HID><<<dim3(8,32,NEXP),256,SM>>>(b2);
    final_kernel<<<NTOK*DIM/256,256>>>(out);
}

// round 6
// speedup vs baseline: 2.7463x; 1.9999x over previous
#include <cuda_runtime.h>
#include <cuda_bf16.h>
#include <math.h>
#include <stdint.h>

#define BB 2
#define TT 2048
#define DIM 1024
#define NTOK 4096
#define NEXP 8
#define HID 4096
#define MAXTOK 4096
typedef __nv_bfloat16 bf16;

// ---------- scratch ----------
__device__ bf16 g_h_hi[NTOK*DIM], g_h_lo[NTOK*DIM];
__device__ bf16 g_q_hi[32*2048*64], g_q_lo[32*2048*64];
__device__ bf16 g_k_hi[32*2048*64], g_k_lo[32*2048*64];
__device__ bf16 g_v_hi[32*2048*64], g_v_lo[32*2048*64];
__device__ bf16 g_y_hi[NTOK*DIM], g_y_lo[NTOK*DIM];
__device__ float g_x1[NTOK*DIM], g_h2f[NTOK*DIM];
__device__ bf16 g_h2_hi[NTOK*DIM], g_h2_lo[NTOK*DIM];
__device__ bf16 g_pool_hi[(size_t)2*NTOK*HID], g_pool_lo[(size_t)2*NTOK*HID];
__device__ float g_c0[NTOK*DIM], g_c1[NTOK*DIM];
__device__ int g_cnt[NEXP], g_basei[NEXP], g_tok[NEXP*MAXTOK], g_slot[NEXP*MAXTOK];
__device__ float g_wt[NEXP*MAXTOK];
__device__ bf16 g_waT_hi[(size_t)3*DIM*DIM], g_waT_lo[(size_t)3*DIM*DIM];
__device__ bf16 g_wpT_hi[(size_t)DIM*DIM],   g_wpT_lo[(size_t)DIM*DIM];
__device__ bf16 g_w1T_hi[(size_t)NEXP*HID*DIM], g_w1T_lo[(size_t)NEXP*HID*DIM];
__device__ bf16 g_w2T_hi[(size_t)NEXP*DIM*HID], g_w2T_lo[(size_t)NEXP*DIM*HID];

// ---------- ptx helpers ----------
__device__ __forceinline__ uint32_t s2u(const void* p){
    uint32_t a; asm("{ .reg .u64 t; cvta.to.shared.u64 t, %1; cvt.u32.u64 %0, t; }":"=r"(a):"l"(p)); return a;
}
__device__ __forceinline__ uint32_t swz(uint32_t o){ return o ^ ((o>>3)&0x70); }
__device__ __forceinline__ void cp16(uint32_t d, const bf16* s, bool v){
    asm volatile("cp.async.cg.shared.global [%0], [%1], 16, %2;"
        ::"r"(d),"l"(__cvta_generic_to_global(s)),"r"(v?16:0));
}
__device__ __forceinline__ void ldx4(uint32_t* r, uint32_t a){
    asm volatile("ldmatrix.sync.aligned.m8n8.x4.shared.b16 {%0,%1,%2,%3},[%4];"
        :"=r"(r[0]),"=r"(r[1]),"=r"(r[2]),"=r"(r[3]):"r"(a));
}
__device__ __forceinline__ void ldx4t(uint32_t* r, uint32_t a){
    asm volatile("ldmatrix.sync.aligned.m8n8.x4.trans.shared.b16 {%0,%1,%2,%3},[%4];"
        :"=r"(r[0]),"=r"(r[1]),"=r"(r[2]),"=r"(r[3]):"r"(a));
}
__device__ __forceinline__ void mma16816(float* d, const uint32_t* a, const uint32_t* b){
    asm volatile("mma.sync.aligned.m16n8k16.row.col.f32.bf16.bf16.f32 "
        "{%0,%1,%2,%3},{%4,%5,%6,%7},{%8,%9},{%0,%1,%2,%3};"
        : "+f"(d[0]),"+f"(d[1]),"+f"(d[2]),"+f"(d[3])
        : "r"(a[0]),"r"(a[1]),"r"(a[2]),"r"(a[3]),"r"(b[0]),"r"(b[1]));
}
__device__ __forceinline__ uint32_t packb(float f0, float f1){
    bf16 b0=__float2bfloat16(f0), b1=__float2bfloat16(f1);
    return (uint32_t)__bfloat16_as_ushort(b0) | ((uint32_t)__bfloat16_as_ushort(b1)<<16);
}

// ---------- small kernels ----------
__global__ void zero_cnt_kernel(){ if(threadIdx.x<NEXP) g_cnt[threadIdx.x]=0; }
__global__ void base_kernel(){
    if(threadIdx.x==0){ int s=0; for(int e=0;e<NEXP;++e){ g_basei[e]=s; s+=g_cnt[e]; } }
}
__global__ void final_kernel(float* __restrict__ out){
    int i = blockIdx.x*256 + threadIdx.x;
    out[i] = g_x1[i] + g_c0[i] + g_c1[i];
}

// ---------- layernorm ----------
template<int WHICH>
__global__ void ln_kernel(const float* __restrict__ in, const float* __restrict__ gam,
                          const float* __restrict__ bet){
    __shared__ float sx[DIM]; __shared__ float red[8];
    const int n=blockIdx.x, tid=threadIdx.x;
    const float* row = (WHICH==0 ? in : g_x1) + (size_t)n*DIM;
    float4 x4 = ((const float4*)row)[tid];
    ((float4*)sx)[tid] = x4;
    float s = x4.x+x4.y+x4.z+x4.w;
    #pragma unroll
    for(int o=16;o;o>>=1) s += __shfl_xor_sync(~0u,s,o);
    if((tid&31)==0) red[tid>>5]=s;
    __syncthreads();
    float mu = (red[0]+red[1]+red[2]+red[3]+red[4]+red[5]+red[6]+red[7])*(1.f/DIM);
    float sq=0.f;
    #pragma unroll
    for(int p=0;p<4;++p){ float d=sx[tid+p*256]-mu; sq+=d*d; }
    #pragma unroll
    for(int o=16;o;o>>=1) sq += __shfl_xor_sync(~0u,sq,o);
    __syncthreads();
    if((tid&31)==0) red[tid>>5]=sq;
    __syncthreads();
    float var=(red[0]+red[1]+red[2]+red[3]+red[4]+red[5]+red[6]+red[7])*(1.f/DIM);
    float rs = rsqrtf(var+1e-5f);
    #pragma unroll
    for(int p=0;p<4;++p){
        int d=tid+p*256;
        float v = (sx[d]-mu)*rs*gam[d]+bet[d];
        size_t o=(size_t)n*DIM+d;
        bf16 h = __float2bfloat16(v);
        bf16 l = __float2bfloat16(v - __bfloat162float(h));
        if(WHICH==0){ g_h_hi[o]=h; g_h_lo[o]=l; }
        else { g_h2f[o]=v; g_h2_hi[o]=h; g_h2_lo[o]=l; }
    }
}

// ---------- weight transpose + split ----------
template<int WHICH>
__global__ void transpose_split(const float* __restrict__ src){
    constexpr int Kd = (WHICH==3)?HID:DIM;
    constexpr int Nd = (WHICH==0)?3*DIM:((WHICH==2)?HID:DIM);
    bf16 *dhi, *dlo;
    if(WHICH==0){dhi=g_waT_hi;dlo=g_waT_lo;}
    else if(WHICH==1){dhi=g_wpT_hi;dlo=g_wpT_lo;}
    else if(WHICH==2){dhi=g_w1T_hi;dlo=g_w1T_lo;}
    else {dhi=g_w2T_hi;dlo=g_w2T_lo;}
    const int e=blockIdx.z;
    src += (size_t)e*Kd*Nd; dhi += (size_t)e*(size_t)Nd*Kd; dlo += (size_t)e*(size_t)Nd*Kd;
    __shared__ float t[32][33];
    const int n0=blockIdx.x*32, k0=blockIdx.y*32;
    for(int i=threadIdx.y;i<32;i+=8)
        t[i][threadIdx.x] = src[(size_t)(k0+i)*Nd + n0 + threadIdx.x];
    __syncthreads();
    for(int i=threadIdx.y;i<32;i+=8){
        float v = t[threadIdx.x][i];
        size_t o = (size_t)(n0+i)*Kd + k0 + threadIdx.x;
        bf16 h = __float2bfloat16(v);
        dhi[o]=h; dlo[o]=__float2bfloat16(v-__bfloat162float(h));
    }
}

// ---------- mma.sync split-bf16 GEMM: block 128x128, K-step 64, 3-stage ----------
template<int MODE, int N, int K>
__global__ void __launch_bounds__(256,1) tgemm(const float* __restrict__ aux){
    constexpr int NKT = K/64;
    const int e = (MODE>=2)? blockIdx.z : 0;
    int Mrows = NTOK, pbase = 0;
    if(MODE>=2){
        Mrows = g_cnt[e]; pbase = g_basei[e];
        if((int)blockIdx.y*128 >= Mrows) return;
    }
    extern __shared__ char smem[];
    const uint32_t sb = s2u(smem);
    const int tid = threadIdx.x, lane = tid&31, wid = tid>>5;
    const int wm = wid>>2, wn = wid&3;
    const int m0 = blockIdx.y*128, n0 = blockIdx.x*128;

    const bf16 *Ahi,*Alo,*Bhi,*Blo;
    if(MODE==0){ Ahi=g_h_hi; Alo=g_h_lo; Bhi=g_waT_hi; Blo=g_waT_lo; }
    else if(MODE==1){ Ahi=g_y_hi; Alo=g_y_lo; Bhi=g_wpT_hi; Blo=g_wpT_lo; }
    else if(MODE==2){ Ahi=g_h2_hi; Alo=g_h2_lo;
        Bhi=g_w1T_hi+(size_t)e*HID*DIM; Blo=g_w1T_lo+(size_t)e*HID*DIM; }
    else { Ahi=g_pool_hi; Alo=g_pool_lo;
        Bhi=g_w2T_hi+(size_t)e*DIM*HID; Blo=g_w2T_lo+(size_t)e*DIM*HID; }

    const bf16 *pah[4],*pal[4],*pbh[4],*pbl[4]; uint32_t doff[4]; bool av[4];
    #pragma unroll
    for(int i=0;i<4;++i){
        int idx=tid+i*256, r=idx>>3, c=idx&7;
        doff[i]=swz((uint32_t)(r*128+c*16));
        int gm=m0+r; bool v=true; long rg=gm;
        if(MODE==2){ v = gm<Mrows; rg = v ? g_tok[e*MAXTOK+gm] : 0; }
        if(MODE==3){ v = gm<Mrows; rg = (long)pbase + (v?gm:0); }
        pah[i]=Ahi+(size_t)rg*K+c*8; pal[i]=Alo+(size_t)rg*K+c*8; av[i]=v;
        pbh[i]=Bhi+(size_t)(n0+r)*K+c*8; pbl[i]=Blo+(size_t)(n0+r)*K+c*8;
    }

    float acc[4][4][4];
    #pragma unroll
    for(int a=0;a<4;++a)
        #pragma unroll
        for(int b=0;b<4;++b)
            #pragma unroll
            for(int c=0;c<4;++c) acc[a][b][c]=0.f;

    const int arow = wm*64 + (lane&15), achk = lane>>4;
    const int brow = wn*32 + ((lane>>4)&1)*8 + (lane&7), bchk = (lane>>3)&1;

    auto issue = [&](int kt){
        const uint32_t st = sb + (kt%3)*65536;
        const int ko = kt*64;
        #pragma unroll
        for(int i=0;i<4;++i){
            cp16(st+doff[i],        pah[i]+ko, av[i]);
            cp16(st+16384+doff[i],  pal[i]+ko, av[i]);
            cp16(st+32768+doff[i],  pbh[i]+ko, true);
            cp16(st+49152+doff[i],  pbl[i]+ko, true);
        }
        asm volatile("cp.async.commit_group;":::"memory");
    };

    issue(0); issue(1);
    for(int kt=0; kt<NKT; ++kt){
        if(kt+1<NKT){ asm volatile("cp.async.wait_group 1;":::"memory"); }
        else        { asm volatile("cp.async.wait_group 0;":::"memory"); }
        __syncthreads();
        if(kt+2<NKT) issue(kt+2);
        const uint32_t st = sb + (kt%3)*65536;
        #pragma unroll
        for(int k16=0;k16<4;++k16){
            uint32_t ah[4][4], al[4][4], bh[4][2], bl[4][2];
            #pragma unroll
            for(int mi=0;mi<4;++mi){
                uint32_t off = (uint32_t)((arow+mi*16)*128 + k16*32 + achk*16);
                ldx4(ah[mi], st + swz(off));
                ldx4(al[mi], st + 16384 + swz(off));
            }
            #pragma unroll
            for(int np=0;np<2;++np){
                uint32_t off = (uint32_t)((brow+np*16)*128 + k16*32 + bchk*16);
                uint32_t r[4];
                ldx4(r, st + 32768 + swz(off));
                bh[np*2][0]=r[0]; bh[np*2][1]=r[1]; bh[np*2+1][0]=r[2]; bh[np*2+1][1]=r[3];
                ldx4(r, st + 49152 + swz(off));
                bl[np*2][0]=r[0]; bl[np*2][1]=r[1]; bl[np*2+1][0]=r[2]; bl[np*2+1][1]=r[3];
            }
            #pragma unroll
            for(int mi=0;mi<4;++mi)
                #pragma unroll
                for(int ni=0;ni<4;++ni){
                    mma16816(acc[mi][ni], ah[mi], bh[ni]);
                    mma16816(acc[mi][ni], ah[mi], bl[ni]);
                    mma16816(acc[mi][ni], al[mi], bh[ni]);
                }
        }
        __syncthreads();
    }

    const int r0 = lane>>2, c2 = (lane&3)*2;
    const float* bias = (MODE>=2)? (aux+(size_t)e*N) : aux;
    #pragma unroll
    for(int mi=0;mi<4;++mi){
        #pragma unroll
        for(int half=0; half<2; ++half){
            const int m = m0 + wm*64 + mi*16 + r0 + half*8;
            if(MODE>=2 && m>=Mrows) continue;
            int tok=0, slot=0; float wgt=0.f;
            if(MODE==3){ int ix=e*MAXTOK+m; tok=g_tok[ix]; wgt=g_wt[ix]; slot=g_slot[ix]; }
            #pragma unroll
            for(int ni=0;ni<4;++ni){
                const int col = n0 + wn*32 + ni*8 + c2;
                float d0 = acc[mi][ni][half*2], d1 = acc[mi][ni][half*2+1];
                if(MODE==0){
                    const int which = col>>10, r = col&1023, h = r>>6, d = r&63;
                    const int b = m>>11, t = m&2047;
                    size_t o = ((size_t)(b*16+h)*2048 + t)*64 + d;
                    bf16 *ph, *pl;
                    if(which==0){ d0*=0.125f; d1*=0.125f; ph=g_q_hi; pl=g_q_lo; }
                    else if(which==1){ ph=g_k_hi; pl=g_k_lo; }
                    else { ph=g_v_hi; pl=g_v_lo; }
                    bf16 h0=__float2bfloat16(d0), h1=__float2bfloat16(d1);
                    ph[o]=h0; ph[o+1]=h1;
                    pl[o]=__float2bfloat16(d0-__bfloat162float(h0));
                    pl[o+1]=__float2bfloat16(d1-__bfloat162float(h1));
                } else if(MODE==1){
                    const float* rx=aux+(size_t)m*N+col;
                    float* dst=g_x1+(size_t)m*N+col;
                    dst[0]=rx[0]+d0; dst[1]=rx[1]+d1;
                } else if(MODE==2){
                    size_t prow=(size_t)(pbase+m);
                    float v0=d0+bias[col], v1=d1+bias[col+1];
                    float gg0=0.5f*v0*(1.f+erff(v0*0.70710678f));
                    float gg1=0.5f*v1*(1.f+erff(v1*0.70710678f));
                    bf16 h0=__float2bfloat16(gg0), h1=__float2bfloat16(gg1);
                    g_pool_hi[prow*HID+col]=h0;   g_pool_hi[prow*HID+col+1]=h1;
                    g_pool_lo[prow*HID+col]=__float2bfloat16(gg0-__bfloat162float(h0));
                    g_pool_lo[prow*HID+col+1]=__float2bfloat16(gg1-__bfloat162float(h1));
                } else {
                    float* dst=(slot?g_c1:g_c0)+(size_t)tok*DIM+col;
                    dst[0]=wgt*(d0+bias[col]); dst[1]=wgt*(d1+bias[col+1]);
                }
            }
        }
    }
}

// ---------- tensor-core flash attention: 128 q rows/CTA, 64-kv chunks, 3-stage KV ----------
// smem: Qhi 0, Qlo 16K, stage p at 32K+p*32K (p=0,1,2): {Khi,Klo,Vhi,Vlo} 8K each
__global__ void __launch_bounds__(256,1) attn_mma(){
    extern __shared__ char smem[];
    const uint32_t sb = s2u(smem);
    const int tid=threadIdx.x, lane=tid&31, wid=tid>>5;
    const int bh = blockIdx.y;
    const int qt = (gridDim.x-1) - blockIdx.x;
    const int q0 = qt*128;
    const size_t pbase = (size_t)bh*2048*64;

    #pragma unroll
    for(int i=0;i<4;++i){
        int idx=tid+i*256, r=idx>>3, c=idx&7;
        uint32_t off = swz((uint32_t)(r*128+c*16));
        cp16(sb+off,        g_q_hi + pbase + (size_t)(q0+r)*64 + c*8, true);
        cp16(sb+16384+off,  g_q_lo + pbase + (size_t)(q0+r)*64 + c*8, true);
    }
    auto issueKV = [&](int kb){
        const uint32_t st = sb + 32768 + (kb%3)*32768;
        #pragma unroll
        for(int i=0;i<2;++i){
            int idx=tid+i*256, r=idx>>3, c=idx&7;
            uint32_t off = swz((uint32_t)(r*128+c*16));
            size_t src = pbase + (size_t)(kb*64+r)*64 + c*8;
            cp16(st+off,        g_k_hi+src, true);
            cp16(st+8192+off,   g_k_lo+src, true);
            cp16(st+16384+off,  g_v_hi+src, true);
            cp16(st+24576+off,  g_v_lo+src, true);
        }
        asm volatile("cp.async.commit_group;":::"memory");
    };
    const int kbmax = 2*qt+1;
    issueKV(0);                 // group0 = Q + KV0
    issueKV(1);                 // group1 = KV1

    asm volatile("cp.async.wait_group 1;":::"memory");
    __syncthreads();
    uint32_t qh[4][4], ql[4][4];
    {
        const int qrow = wid*16 + (lane&15), qchk = lane>>4;
        #pragma unroll
        for(int k16=0;k16<4;++k16){
            uint32_t off = swz((uint32_t)(qrow*128 + k16*32 + qchk*16));
            ldx4(qh[k16], sb+off);
            ldx4(ql[k16], sb+16384+off);
        }
    }

    float O[8][4], mstat[2], lstat[2];
    #pragma unroll
    for(int t=0;t<8;++t){ O[t][0]=0;O[t][1]=0;O[t][2]=0;O[t][3]=0; }
    mstat[0]=mstat[1]=-1e30f; lstat[0]=lstat[1]=0.f;

    const int rloc = lane>>2, cloc = (lane&3)*2;
    const int brow_b = ((lane>>4)&1)*8 + (lane&7), bchk = (lane>>3)&1;
    const int vrow_b = ((lane>>3)&1)*8 + (lane&7), vcol_b = ((lane>>4)&1)*8;

    for(int kb=0; kb<=kbmax; ++kb){
        if(kb<kbmax){ asm volatile("cp.async.wait_group 1;":::"memory"); }
        else        { asm volatile("cp.async.wait_group 0;":::"memory"); }
        __syncthreads();
        if(kb+2<=kbmax) issueKV(kb+2);          // stage (kb+2)%3: idle since kb-1's sync
        const uint32_t st = sb + 32768 + (kb%3)*32768;

        float s[8][4];
        #pragma unroll
        for(int t=0;t<8;++t){ s[t][0]=0;s[t][1]=0;s[t][2]=0;s[t][3]=0; }
        #pragma unroll
        for(int k16=0;k16<4;++k16){
            uint32_t bkh[8][2], bkl[8][2];
            #pragma unroll
            for(int n16=0;n16<4;++n16){
                uint32_t off = swz((uint32_t)((n16*16+brow_b)*128 + k16*32 + bchk*16));
                uint32_t r[4];
                ldx4(r, st+off);
                bkh[n16*2][0]=r[0]; bkh[n16*2][1]=r[1]; bkh[n16*2+1][0]=r[2]; bkh[n16*2+1][1]=r[3];
                ldx4(r, st+8192+off);
                bkl[n16*2][0]=r[0]; bkl[n16*2][1]=r[1]; bkl[n16*2+1][0]=r[2]; bkl[n16*2+1][1]=r[3];
            }
            #pragma unroll
            for(int t=0;t<8;++t){
                mma16816(s[t], qh[k16], bkh[t]);
                mma16816(s[t], qh[k16], bkl[t]);
                mma16816(s[t], ql[k16], bkh[t]);
            }
        }
        if(kb >= 2*qt){
            const int row0 = q0 + wid*16 + rloc;
            #pragma unroll
            for(int t=0;t<8;++t){
                int c0 = kb*64 + t*8 + cloc;
                if(c0   > row0  ) s[t][0]=-1e30f;
                if(c0+1 > row0  ) s[t][1]=-1e30f;
                if(c0   > row0+8) s[t][2]=-1e30f;
                if(c0+1 > row0+8) s[t][3]=-1e30f;
            }
        }
        float corr[2];
        #pragma unroll
        for(int rh=0; rh<2; ++rh){
            float mt=-1e30f;
            #pragma unroll
            for(int t=0;t<8;++t) mt = fmaxf(mt, fmaxf(s[t][rh*2], s[t][rh*2+1]));
            mt = fmaxf(mt, __shfl_xor_sync(~0u, mt, 1, 4));
            mt = fmaxf(mt, __shfl_xor_sync(~0u, mt, 2, 4));
            float mn = fmaxf(mstat[rh], mt);
            corr[rh] = __expf(mstat[rh]-mn); mstat[rh]=mn;
            float rs=0.f;
            #pragma unroll
            for(int t=0;t<8;++t){
                float p0=__expf(s[t][rh*2]-mn), p1=__expf(s[t][rh*2+1]-mn);
                s[t][rh*2]=p0; s[t][rh*2+1]=p1; rs += p0+p1;
            }
            rs += __shfl_xor_sync(~0u, rs, 1, 4);
            rs += __shfl_xor_sync(~0u, rs, 2, 4);
            lstat[rh] = lstat[rh]*corr[rh] + rs;
        }
        #pragma unroll
        for(int t=0;t<8;++t){
            O[t][0]*=corr[0]; O[t][1]*=corr[0]; O[t][2]*=corr[1]; O[t][3]*=corr[1];
        }
        uint32_t ph[4][4], pl[4][4];
        #pragma unroll
        for(int k16=0;k16<4;++k16){
            #pragma unroll
            for(int half=0; half<2; ++half){
                const int t = 2*k16+half;
                float f0=s[t][0], f1=s[t][1], f2=s[t][2], f3=s[t][3];
                ph[k16][half*2]   = packb(f0,f1);
                ph[k16][half*2+1] = packb(f2,f3);
                bf16 h0=__float2bfloat16(f0), h1=__float2bfloat16(f1);
                bf16 h2=__float2bfloat16(f2), h3=__float2bfloat16(f3);
                pl[k16][half*2]   = packb(f0-__bfloat162float(h0), f1-__bfloat162float(h1));
                pl[k16][half*2+1] = packb(f2-__bfloat162float(h2), f3-__bfloat162float(h3));
            }
        }
        #pragma unroll
        for(int k16=0;k16<4;++k16){
            uint32_t bvh[8][2], bvl[8][2];
            #pragma unroll
            for(int d16=0;d16<4;++d16){
                uint32_t off = swz((uint32_t)((k16*16+vrow_b)*128 + (d16*16+vcol_b)*2));
                uint32_t r[4];
                ldx4t(r, st+16384+off);
                bvh[d16*2][0]=r[0]; bvh[d16*2][1]=r[1]; bvh[d16*2+1][0]=r[2]; bvh[d16*2+1][1]=r[3];
                ldx4t(r, st+24576+off);
                bvl[d16*2][0]=r[0]; bvl[d16*2][1]=r[1]; bvl[d16*2+1][0]=r[2]; bvl[d16*2+1][1]=r[3];
            }
            #pragma unroll
            for(int t=0;t<8;++t){
                mma16816(O[t], ph[k16], bvh[t]);
                mma16816(O[t], ph[k16], bvl[t]);
                mma16816(O[t], pl[k16], bvh[t]);
            }
        }
        __syncthreads();
    }

    const int b = bh>>4, h = bh&15;
    #pragma unroll
    for(int rh=0; rh<2; ++rh){
        const float inv = 1.f/lstat[rh];
        const int row = q0 + wid*16 + rloc + rh*8;
        size_t base = (size_t)(b*TT+row)*DIM + h*64;
        #pragma unroll
        for(int t=0;t<8;++t){
            float v0 = O[t][rh*2]*inv, v1 = O[t][rh*2+1]*inv;
            size_t o = base + t*8 + cloc;
            bf16 h0=__float2bfloat16(v0), h1=__float2bfloat16(v1);
            g_y_hi[o]=h0; g_y_hi[o+1]=h1;
            g_y_lo[o]=__float2bfloat16(v0-__bfloat162float(h0));
            g_y_lo[o+1]=__float2bfloat16(v1-__bfloat162float(h1));
        }
    }
}

// ---------- router ----------
__global__ void router_kernel(const float* __restrict__ wr){
    const int n=blockIdx.x, tid=threadIdx.x;
    float acc[NEXP];
    #pragma unroll
    for(int e=0;e<NEXP;++e) acc[e]=0.f;
    const float* row=g_h2f+(size_t)n*DIM;
    for(int d=tid;d<DIM;d+=128){
        float hv=row[d];
        #pragma unroll
        for(int e=0;e<NEXP;++e) acc[e]+=hv*wr[d*NEXP+e];
    }
    __shared__ float sm[4][NEXP];
    #pragma unroll
    for(int e=0;e<NEXP;++e){
        float v=acc[e];
        #pragma unroll
        for(int o=16;o;o>>=1) v+=__shfl_xor_sync(~0u,v,o);
        if((tid&31)==0) sm[tid>>5][e]=v;
    }
    __syncthreads();
    if(tid==0){
        float lg[NEXP];
        #pragma unroll
        for(int e=0;e<NEXP;++e) lg[e]=sm[0][e]+sm[1][e]+sm[2][e]+sm[3][e];
        int e0=0;
        #pragma unroll
        for(int e=1;e<NEXP;++e) if(lg[e]>lg[e0]) e0=e;
        int e1=-1;
        #pragma unroll
        for(int e=0;e<NEXP;++e) if(e!=e0 && (e1<0||lg[e]>lg[e1])) e1=e;
        float w0=1.f/(1.f+__expf(lg[e1]-lg[e0])), w1=1.f-w0;
        int p0=atomicAdd(&g_cnt[e0],1);
        g_tok[e0*MAXTOK+p0]=n; g_wt[e0*MAXTOK+p0]=w0; g_slot[e0*MAXTOK+p0]=0;
        int p1=atomicAdd(&g_cnt[e1],1);
        g_tok[e1*MAXTOK+p1]=n; g_wt[e1*MAXTOK+p1]=w1; g_slot[e1*MAXTOK+p1]=1;
    }
}

// ---------- launch ----------
extern "C" void kernel_launch(void* const* d_in, const int* in_sizes, int n_in,
                              void* d_out, int out_size){
    const float* x      =(const float*)d_in[0];
    const float* ln1_g  =(const float*)d_in[1];
    const float* ln1_b  =(const float*)d_in[2];
    const float* w_attn =(const float*)d_in[3];
    const float* w_proj =(const float*)d_in[4];
    const float* ln2_g  =(const float*)d_in[5];
    const float* ln2_b  =(const float*)d_in[6];
    const float* w_rtr  =(const float*)d_in[7];
    const float* w1     =(const float*)d_in[8];
    const float* b1     =(const float*)d_in[9];
    const float* w2     =(const float*)d_in[10];
    const float* b2     =(const float*)d_in[11];
    float* out=(float*)d_out;

    const int SMG = 196608;
    cudaFuncSetAttribute(tgemm<0,3*DIM,DIM>, cudaFuncAttributeMaxDynamicSharedMemorySize, SMG);
    cudaFuncSetAttribute(tgemm<1,DIM,DIM>,   cudaFuncAttributeMaxDynamicSharedMemorySize, SMG);
    cudaFuncSetAttribute(tgemm<2,HID,DIM>,   cudaFuncAttributeMaxDynamicSharedMemorySize, SMG);
    cudaFuncSetAttribute(tgemm<3,DIM,HID>,   cudaFuncAttributeMaxDynamicSharedMemorySize, SMG);
    const int SMA = 131072;
    cudaFuncSetAttribute(attn_mma, cudaFuncAttributeMaxDynamicSharedMemorySize, SMA);

    zero_cnt_kernel<<<1,32>>>();
    transpose_split<0><<<dim3(96,32,1), dim3(32,8)>>>(w_attn);
    transpose_split<1><<<dim3(32,32,1), dim3(32,8)>>>(w_proj);
    transpose_split<2><<<dim3(128,32,NEXP), dim3(32,8)>>>(w1);
    transpose_split<3><<<dim3(32,128,NEXP), dim3(32,8)>>>(w2);

    ln_kernel<0><<<NTOK,256>>>(x, ln1_g, ln1_b);
    tgemm<0,3*DIM,DIM><<<dim3(24,32,1),256,SMG>>>(nullptr);
    attn_mma<<<dim3(TT/128, BB*16),256,SMA>>>();
    tgemm<1,DIM,DIM><<<dim3(8,32,1),256,SMG>>>(x);
    ln_kernel<1><<<NTOK,256>>>(nullptr, ln2_g, ln2_b);
    router_kernel<<<NTOK,128>>>(w_rtr);
    base_kernel<<<1,32>>>();
    tgemm<2,HID,DIM><<<dim3(32,32,NEXP),256,SMG>>>(b1);
    tgemm<3,DIM,HID><<<dim3(8,32,NEXP),256,SMG>>>(b2);
    final_kernel<<<NTOK*DIM/256,256>>>(out);
}

// round 7
// speedup vs baseline: 3.0575x; 1.1133x over previous
#include <cuda_runtime.h>
#include <cuda_bf16.h>
#include <math.h>
#include <stdint.h>

#define BB 2
#define TT 2048
#define DIM 1024
#define NTOK 4096
#define NEXP 8
#define HID 4096
#define MAXTOK 4096
typedef __nv_bfloat16 bf16;

// ---------- scratch ----------
__device__ bf16 g_h_hi[NTOK*DIM], g_h_lo[NTOK*DIM];
__device__ bf16 g_q_hi[32*2048*64], g_q_lo[32*2048*64];
__device__ bf16 g_k_hi[32*2048*64], g_k_lo[32*2048*64];
__device__ bf16 g_v_hi[32*2048*64], g_v_lo[32*2048*64];
__device__ bf16 g_y_hi[NTOK*DIM], g_y_lo[NTOK*DIM];
__device__ float g_x1[NTOK*DIM], g_h2f[NTOK*DIM];
__device__ bf16 g_h2_hi[NTOK*DIM], g_h2_lo[NTOK*DIM];
__device__ bf16 g_pool_hi[(size_t)2*NTOK*HID], g_pool_lo[(size_t)2*NTOK*HID];
__device__ float g_c0[NTOK*DIM], g_c1[NTOK*DIM];
__device__ int g_cnt[NEXP], g_basei[NEXP], g_tok[NEXP*MAXTOK], g_slot[NEXP*MAXTOK];
__device__ float g_wt[NEXP*MAXTOK];
__device__ bf16 g_waT_hi[(size_t)3*DIM*DIM], g_waT_lo[(size_t)3*DIM*DIM];
__device__ bf16 g_wpT_hi[(size_t)DIM*DIM],   g_wpT_lo[(size_t)DIM*DIM];
__device__ bf16 g_w1T_hi[(size_t)NEXP*HID*DIM], g_w1T_lo[(size_t)NEXP*HID*DIM];
__device__ bf16 g_w2T_hi[(size_t)NEXP*DIM*HID], g_w2T_lo[(size_t)NEXP*DIM*HID];

// ---------- ptx helpers ----------
__device__ __forceinline__ uint32_t s2u(const void* p){
    uint32_t a; asm("{ .reg .u64 t; cvta.to.shared.u64 t, %1; cvt.u32.u64 %0, t; }":"=r"(a):"l"(p)); return a;
}
__device__ __forceinline__ uint32_t swz(uint32_t o){ return o ^ ((o>>3)&0x70); }
__device__ __forceinline__ void cp16(uint32_t d, const bf16* s, bool v){
    asm volatile("cp.async.cg.shared.global [%0], [%1], 16, %2;"
        ::"r"(d),"l"(__cvta_generic_to_global(s)),"r"(v?16:0));
}
__device__ __forceinline__ void ldx4(uint32_t* r, uint32_t a){
    asm volatile("ldmatrix.sync.aligned.m8n8.x4.shared.b16 {%0,%1,%2,%3},[%4];"
        :"=r"(r[0]),"=r"(r[1]),"=r"(r[2]),"=r"(r[3]):"r"(a));
}
__device__ __forceinline__ void ldx4t(uint32_t* r, uint32_t a){
    asm volatile("ldmatrix.sync.aligned.m8n8.x4.trans.shared.b16 {%0,%1,%2,%3},[%4];"
        :"=r"(r[0]),"=r"(r[1]),"=r"(r[2]),"=r"(r[3]):"r"(a));
}
__device__ __forceinline__ void mma16816(float* d, const uint32_t* a, const uint32_t* b){
    asm volatile("mma.sync.aligned.m16n8k16.row.col.f32.bf16.bf16.f32 "
        "{%0,%1,%2,%3},{%4,%5,%6,%7},{%8,%9},{%0,%1,%2,%3};"
        : "+f"(d[0]),"+f"(d[1]),"+f"(d[2]),"+f"(d[3])
        : "r"(a[0]),"r"(a[1]),"r"(a[2]),"r"(a[3]),"r"(b[0]),"r"(b[1]));
}
__device__ __forceinline__ uint32_t packb(float f0, float f1){
    bf16 b0=__float2bfloat16(f0), b1=__float2bfloat16(f1);
    return (uint32_t)__bfloat16_as_ushort(b0) | ((uint32_t)__bfloat16_as_ushort(b1)<<16);
}

// ---------- small kernels ----------
__global__ void zero_cnt_kernel(){ if(threadIdx.x<NEXP) g_cnt[threadIdx.x]=0; }
__global__ void base_kernel(){
    if(threadIdx.x==0){ int s=0; for(int e=0;e<NEXP;++e){ g_basei[e]=s; s+=g_cnt[e]; } }
}
__global__ void final_kernel(float* __restrict__ out){
    int i = blockIdx.x*256 + threadIdx.x;
    out[i] = g_x1[i] + g_c0[i] + g_c1[i];
}

// ---------- layernorm ----------
template<int WHICH>
__global__ void ln_kernel(const float* __restrict__ in, const float* __restrict__ gam,
                          const float* __restrict__ bet){
    __shared__ float sx[DIM]; __shared__ float red[8];
    const int n=blockIdx.x, tid=threadIdx.x;
    const float* row = (WHICH==0 ? in : g_x1) + (size_t)n*DIM;
    float4 x4 = ((const float4*)row)[tid];
    ((float4*)sx)[tid] = x4;
    float s = x4.x+x4.y+x4.z+x4.w;
    #pragma unroll
    for(int o=16;o;o>>=1) s += __shfl_xor_sync(~0u,s,o);
    if((tid&31)==0) red[tid>>5]=s;
    __syncthreads();
    float mu = (red[0]+red[1]+red[2]+red[3]+red[4]+red[5]+red[6]+red[7])*(1.f/DIM);
    float sq=0.f;
    #pragma unroll
    for(int p=0;p<4;++p){ float d=sx[tid+p*256]-mu; sq+=d*d; }
    #pragma unroll
    for(int o=16;o;o>>=1) sq += __shfl_xor_sync(~0u,sq,o);
    __syncthreads();
    if((tid&31)==0) red[tid>>5]=sq;
    __syncthreads();
    float var=(red[0]+red[1]+red[2]+red[3]+red[4]+red[5]+red[6]+red[7])*(1.f/DIM);
    float rs = rsqrtf(var+1e-5f);
    #pragma unroll
    for(int p=0;p<4;++p){
        int d=tid+p*256;
        float v = (sx[d]-mu)*rs*gam[d]+bet[d];
        size_t o=(size_t)n*DIM+d;
        bf16 h = __float2bfloat16(v);
        bf16 l = __float2bfloat16(v - __bfloat162float(h));
        if(WHICH==0){ g_h_hi[o]=h; g_h_lo[o]=l; }
        else { g_h2f[o]=v; g_h2_hi[o]=h; g_h2_lo[o]=l; }
    }
}

// ---------- weight transpose + split (vectorized stores) ----------
template<int WHICH>
__global__ void transpose_split(const float* __restrict__ src){
    constexpr int Kd = (WHICH==3)?HID:DIM;
    constexpr int Nd = (WHICH==0)?3*DIM:((WHICH==2)?HID:DIM);
    bf16 *dhi, *dlo;
    if(WHICH==0){dhi=g_waT_hi;dlo=g_waT_lo;}
    else if(WHICH==1){dhi=g_wpT_hi;dlo=g_wpT_lo;}
    else if(WHICH==2){dhi=g_w1T_hi;dlo=g_w1T_lo;}
    else {dhi=g_w2T_hi;dlo=g_w2T_lo;}
    const int e=blockIdx.z;
    src += (size_t)e*Kd*Nd; dhi += (size_t)e*(size_t)Nd*Kd; dlo += (size_t)e*(size_t)Nd*Kd;
    __shared__ float t[32][33];
    const int n0=blockIdx.x*32, k0=blockIdx.y*32;
    const int tx=threadIdx.x, ty=threadIdx.y;
    for(int i=ty;i<32;i+=8)
        t[i][tx] = src[(size_t)(k0+i)*Nd + n0 + tx];
    __syncthreads();
    const int tid = ty*32+tx;
    const int wq = tid&7, nn = tid>>3;   // k-quad, n-row
    float v0=t[wq*4+0][nn], v1=t[wq*4+1][nn], v2=t[wq*4+2][nn], v3=t[wq*4+3][nn];
    bf16 h0=__float2bfloat16(v0), h1=__float2bfloat16(v1);
    bf16 h2=__float2bfloat16(v2), h3=__float2bfloat16(v3);
    size_t o = (size_t)(n0+nn)*Kd + k0 + wq*4;
    uint2 hv, lv;
    hv.x = (uint32_t)__bfloat16_as_ushort(h0) | ((uint32_t)__bfloat16_as_ushort(h1)<<16);
    hv.y = (uint32_t)__bfloat16_as_ushort(h2) | ((uint32_t)__bfloat16_as_ushort(h3)<<16);
    lv.x = packb(v0-__bfloat162float(h0), v1-__bfloat162float(h1));
    lv.y = packb(v2-__bfloat162float(h2), v3-__bfloat162float(h3));
    *(uint2*)&dhi[o] = hv;
    *(uint2*)&dlo[o] = lv;
}

// ---------- mma.sync split-bf16 GEMM: block 128x256, warp 64x64, K-step 64, 2-stage ----------
// stage layout (96KB): Ahi 0, Alo 16K, Bhi 32K(32KB), Blo 64K(32KB)
template<int MODE, int N, int K>
__global__ void __launch_bounds__(256,1) tgemm(const float* __restrict__ aux){
    constexpr int NKT = K/64;
    constexpr int STG = 98304;
    const int e = (MODE>=2)? blockIdx.z : 0;
    int Mrows = NTOK, pbase = 0;
    if(MODE>=2){
        Mrows = g_cnt[e]; pbase = g_basei[e];
        if((int)blockIdx.y*128 >= Mrows) return;
    }
    extern __shared__ char smem[];
    const uint32_t sb = s2u(smem);
    const int tid = threadIdx.x, lane = tid&31, wid = tid>>5;
    const int wm = wid>>2, wn = wid&3;        // warps 2x4, warp tile 64x64
    const int m0 = blockIdx.y*128, n0 = blockIdx.x*256;

    const bf16 *Ahi,*Alo,*Bhi,*Blo;
    if(MODE==0){ Ahi=g_h_hi; Alo=g_h_lo; Bhi=g_waT_hi; Blo=g_waT_lo; }
    else if(MODE==1){ Ahi=g_y_hi; Alo=g_y_lo; Bhi=g_wpT_hi; Blo=g_wpT_lo; }
    else if(MODE==2){ Ahi=g_h2_hi; Alo=g_h2_lo;
        Bhi=g_w1T_hi+(size_t)e*HID*DIM; Blo=g_w1T_lo+(size_t)e*HID*DIM; }
    else { Ahi=g_pool_hi; Alo=g_pool_lo;
        Bhi=g_w2T_hi+(size_t)e*DIM*HID; Blo=g_w2T_lo+(size_t)e*DIM*HID; }

    // load plan: base smem offset for chunk0; chunk i adds i*4096 (swizzle-invariant)
    const uint32_t d0 = swz((uint32_t)((tid>>3)*128 + (tid&7)*16));
    // A: 4 chunks (rows (tid>>3)+i*32), possibly gathered
    const bf16 *pah[4], *pal[4]; bool av[4];
    #pragma unroll
    for(int i=0;i<4;++i){
        int r = (tid>>3) + i*32, gm = m0 + r;
        bool v = true; long rg = gm;
        if(MODE==2){ v = gm<Mrows; rg = v ? g_tok[e*MAXTOK+gm] : 0; }
        if(MODE==3){ v = gm<Mrows; rg = (long)pbase + (v?gm:0); }
        pah[i]=Ahi+(size_t)rg*K+(tid&7)*8; pal[i]=Alo+(size_t)rg*K+(tid&7)*8; av[i]=v;
    }
    // B: 8 chunks, affine
    const bf16 *pb_h = Bhi + (size_t)(n0 + (tid>>3))*K + (tid&7)*8;
    const bf16 *pb_l = Blo + (size_t)(n0 + (tid>>3))*K + (tid&7)*8;

    float acc[4][8][4];
    #pragma unroll
    for(int a=0;a<4;++a)
        #pragma unroll
        for(int b=0;b<8;++b)
            #pragma unroll
            for(int c=0;c<4;++c) acc[a][b][c]=0.f;

    const int arow = wm*64 + (lane&15), achk = lane>>4;
    const int brow_b = wn*64 + ((lane>>4)&1)*8 + (lane&7), bchk = (lane>>3)&1;

    auto issue = [&](int kt){
        const uint32_t st = sb + (kt&1)*STG;
        const int ko = kt*64;
        #pragma unroll
        for(int i=0;i<4;++i){
            cp16(st+d0+i*4096,        pah[i]+ko, av[i]);
            cp16(st+16384+d0+i*4096,  pal[i]+ko, av[i]);
        }
        #pragma unroll
        for(int i=0;i<8;++i){
            cp16(st+32768+d0+i*4096,  pb_h + (size_t)i*32*K + ko, true);
            cp16(st+65536+d0+i*4096,  pb_l + (size_t)i*32*K + ko, true);
        }
        asm volatile("cp.async.commit_group;":::"memory");
    };

    issue(0);
    for(int kt=0; kt<NKT; ++kt){
        if(kt+1<NKT){ issue(kt+1); asm volatile("cp.async.wait_group 1;":::"memory"); }
        else        { asm volatile("cp.async.wait_group 0;":::"memory"); }
        __syncthreads();
        const uint32_t st = sb + (kt&1)*STG;
        #pragma unroll
        for(int k16=0;k16<4;++k16){
            uint32_t ah[4][4], al[4][4];
            #pragma unroll
            for(int mi=0;mi<4;++mi){
                uint32_t off = swz((uint32_t)((arow+mi*16)*128 + k16*32 + achk*16));
                ldx4(ah[mi], st + off);
                ldx4(al[mi], st + 16384 + off);
            }
            #pragma unroll
            for(int n16=0;n16<4;++n16){
                uint32_t off = swz((uint32_t)((brow_b+n16*16)*128 + k16*32 + bchk*16));
                uint32_t rh[4], rl[4];
                ldx4(rh, st + 32768 + off);
                ldx4(rl, st + 65536 + off);
                #pragma unroll
                for(int mi=0;mi<4;++mi){
                    mma16816(acc[mi][n16*2],   ah[mi], rh);
                    mma16816(acc[mi][n16*2],   ah[mi], rl);
                    mma16816(acc[mi][n16*2],   al[mi], rh);
                    mma16816(acc[mi][n16*2+1], ah[mi], rh+2);
                    mma16816(acc[mi][n16*2+1], ah[mi], rl+2);
                    mma16816(acc[mi][n16*2+1], al[mi], rh+2);
                }
            }
        }
        __syncthreads();
    }

    const int r0 = lane>>2, c2 = (lane&3)*2;
    const float* bias = (MODE>=2)? (aux+(size_t)e*N) : aux;
    #pragma unroll
    for(int mi=0;mi<4;++mi){
        #pragma unroll
        for(int half=0; half<2; ++half){
            const int m = m0 + wm*64 + mi*16 + r0 + half*8;
            if(MODE>=2 && m>=Mrows) continue;
            int tok=0, slot=0; float wgt=0.f;
            if(MODE==3){ int ix=e*MAXTOK+m; tok=g_tok[ix]; wgt=g_wt[ix]; slot=g_slot[ix]; }
            #pragma unroll
            for(int ni=0;ni<8;++ni){
                const int col = n0 + wn*64 + ni*8 + c2;
                float dd0 = acc[mi][ni][half*2], dd1 = acc[mi][ni][half*2+1];
                if(MODE==0){
                    const int which = col>>10, r = col&1023, h = r>>6, d = r&63;
                    const int b = m>>11, t = m&2047;
                    size_t o = ((size_t)(b*16+h)*2048 + t)*64 + d;
                    bf16 *ph, *pl;
                    if(which==0){ dd0*=0.125f; dd1*=0.125f; ph=g_q_hi; pl=g_q_lo; }
                    else if(which==1){ ph=g_k_hi; pl=g_k_lo; }
                    else { ph=g_v_hi; pl=g_v_lo; }
                    bf16 h0=__float2bfloat16(dd0), h1=__float2bfloat16(dd1);
                    *(uint32_t*)&ph[o] = (uint32_t)__bfloat16_as_ushort(h0)
                                       | ((uint32_t)__bfloat16_as_ushort(h1)<<16);
                    *(uint32_t*)&pl[o] = packb(dd0-__bfloat162float(h0), dd1-__bfloat162float(h1));
                } else if(MODE==1){
                    const float* rx=aux+(size_t)m*N+col;
                    float2 w; w.x = rx[0]+dd0; w.y = rx[1]+dd1;
                    *(float2*)&g_x1[(size_t)m*N+col] = w;
                } else if(MODE==2){
                    size_t prow=(size_t)(pbase+m);
                    float v0=dd0+bias[col], v1=dd1+bias[col+1];
                    float gg0=0.5f*v0*(1.f+erff(v0*0.70710678f));
                    float gg1=0.5f*v1*(1.f+erff(v1*0.70710678f));
                    bf16 h0=__float2bfloat16(gg0), h1=__float2bfloat16(gg1);
                    *(uint32_t*)&g_pool_hi[prow*HID+col] =
                        (uint32_t)__bfloat16_as_ushort(h0) | ((uint32_t)__bfloat16_as_ushort(h1)<<16);
                    *(uint32_t*)&g_pool_lo[prow*HID+col] =
                        packb(gg0-__bfloat162float(h0), gg1-__bfloat162float(h1));
                } else {
                    float2 w; w.x = wgt*(dd0+bias[col]); w.y = wgt*(dd1+bias[col+1]);
                    *(float2*)&((slot?g_c1:g_c0)[(size_t)tok*DIM+col]) = w;
                }
            }
        }
    }
}

// ---------- tensor-core flash attention (unchanged from R6) ----------
__global__ void __launch_bounds__(256,1) attn_mma(){
    extern __shared__ char smem[];
    const uint32_t sb = s2u(smem);
    const int tid=threadIdx.x, lane=tid&31, wid=tid>>5;
    const int bh = blockIdx.y;
    const int qt = (gridDim.x-1) - blockIdx.x;
    const int q0 = qt*128;
    const size_t pbase = (size_t)bh*2048*64;

    #pragma unroll
    for(int i=0;i<4;++i){
        int idx=tid+i*256, r=idx>>3, c=idx&7;
        uint32_t off = swz((uint32_t)(r*128+c*16));
        cp16(sb+off,        g_q_hi + pbase + (size_t)(q0+r)*64 + c*8, true);
        cp16(sb+16384+off,  g_q_lo + pbase + (size_t)(q0+r)*64 + c*8, true);
    }
    auto issueKV = [&](int kb){
        const uint32_t st = sb + 32768 + (kb%3)*32768;
        #pragma unroll
        for(int i=0;i<2;++i){
            int idx=tid+i*256, r=idx>>3, c=idx&7;
            uint32_t off = swz((uint32_t)(r*128+c*16));
            size_t src = pbase + (size_t)(kb*64+r)*64 + c*8;
            cp16(st+off,        g_k_hi+src, true);
            cp16(st+8192+off,   g_k_lo+src, true);
            cp16(st+16384+off,  g_v_hi+src, true);
            cp16(st+24576+off,  g_v_lo+src, true);
        }
        asm volatile("cp.async.commit_group;":::"memory");
    };
    const int kbmax = 2*qt+1;
    issueKV(0);
    issueKV(1);

    asm volatile("cp.async.wait_group 1;":::"memory");
    __syncthreads();
    uint32_t qh[4][4], ql[4][4];
    {
        const int qrow = wid*16 + (lane&15), qchk = lane>>4;
        #pragma unroll
        for(int k16=0;k16<4;++k16){
            uint32_t off = swz((uint32_t)(qrow*128 + k16*32 + qchk*16));
            ldx4(qh[k16], sb+off);
            ldx4(ql[k16], sb+16384+off);
        }
    }

    float O[8][4], mstat[2], lstat[2];
    #pragma unroll
    for(int t=0;t<8;++t){ O[t][0]=0;O[t][1]=0;O[t][2]=0;O[t][3]=0; }
    mstat[0]=mstat[1]=-1e30f; lstat[0]=lstat[1]=0.f;

    const int rloc = lane>>2, cloc = (lane&3)*2;
    const int brow_b = ((lane>>4)&1)*8 + (lane&7), bchk = (lane>>3)&1;
    const int vrow_b = ((lane>>3)&1)*8 + (lane&7), vcol_b = ((lane>>4)&1)*8;

    for(int kb=0; kb<=kbmax; ++kb){
        if(kb<kbmax){ asm volatile("cp.async.wait_group 1;":::"memory"); }
        else        { asm volatile("cp.async.wait_group 0;":::"memory"); }
        __syncthreads();
        if(kb+2<=kbmax) issueKV(kb+2);
        const uint32_t st = sb + 32768 + (kb%3)*32768;

        float s[8][4];
        #pragma unroll
        for(int t=0;t<8;++t){ s[t][0]=0;s[t][1]=0;s[t][2]=0;s[t][3]=0; }
        #pragma unroll
        for(int k16=0;k16<4;++k16){
            uint32_t bkh[8][2], bkl[8][2];
            #pragma unroll
            for(int n16=0;n16<4;++n16){
                uint32_t off = swz((uint32_t)((n16*16+brow_b)*128 + k16*32 + bchk*16));
                uint32_t r[4];
                ldx4(r, st+off);
                bkh[n16*2][0]=r[0]; bkh[n16*2][1]=r[1]; bkh[n16*2+1][0]=r[2]; bkh[n16*2+1][1]=r[3];
                ldx4(r, st+8192+off);
                bkl[n16*2][0]=r[0]; bkl[n16*2][1]=r[1]; bkl[n16*2+1][0]=r[2]; bkl[n16*2+1][1]=r[3];
            }
            #pragma unroll
            for(int t=0;t<8;++t){
                mma16816(s[t], qh[k16], bkh[t]);
                mma16816(s[t], qh[k16], bkl[t]);
                mma16816(s[t], ql[k16], bkh[t]);
            }
        }
        if(kb >= 2*qt){
            const int row0 = q0 + wid*16 + rloc;
            #pragma unroll
            for(int t=0;t<8;++t){
                int c0 = kb*64 + t*8 + cloc;
                if(c0   > row0  ) s[t][0]=-1e30f;
                if(c0+1 > row0  ) s[t][1]=-1e30f;
                if(c0   > row0+8) s[t][2]=-1e30f;
                if(c0+1 > row0+8) s[t][3]=-1e30f;
            }
        }
        float corr[2];
        #pragma unroll
        for(int rh=0; rh<2; ++rh){
            float mt=-1e30f;
            #pragma unroll
            for(int t=0;t<8;++t) mt = fmaxf(mt, fmaxf(s[t][rh*2], s[t][rh*2+1]));
            mt = fmaxf(mt, __shfl_xor_sync(~0u, mt, 1, 4));
            mt = fmaxf(mt, __shfl_xor_sync(~0u, mt, 2, 4));
            float mn = fmaxf(mstat[rh], mt);
            corr[rh] = __expf(mstat[rh]-mn); mstat[rh]=mn;
            float rs=0.f;
            #pragma unroll
            for(int t=0;t<8;++t){
                float p0=__expf(s[t][rh*2]-mn), p1=__expf(s[t][rh*2+1]-mn);
                s[t][rh*2]=p0; s[t][rh*2+1]=p1; rs += p0+p1;
            }
            rs += __shfl_xor_sync(~0u, rs, 1, 4);
            rs += __shfl_xor_sync(~0u, rs, 2, 4);
            lstat[rh] = lstat[rh]*corr[rh] + rs;
        }
        #pragma unroll
        for(int t=0;t<8;++t){
            O[t][0]*=corr[0]; O[t][1]*=corr[0]; O[t][2]*=corr[1]; O[t][3]*=corr[1];
        }
        uint32_t ph[4][4], pl[4][4];
        #pragma unroll
        for(int k16=0;k16<4;++k16){
            #pragma unroll
            for(int half=0; half<2; ++half){
                const int t = 2*k16+half;
                float f0=s[t][0], f1=s[t][1], f2=s[t][2], f3=s[t][3];
                ph[k16][half*2]   = packb(f0,f1);
                ph[k16][half*2+1] = packb(f2,f3);
                bf16 h0=__float2bfloat16(f0), h1=__float2bfloat16(f1);
                bf16 h2=__float2bfloat16(f2), h3=__float2bfloat16(f3);
                pl[k16][half*2]   = packb(f0-__bfloat162float(h0), f1-__bfloat162float(h1));
                pl[k16][half*2+1] = packb(f2-__bfloat162float(h2), f3-__bfloat162float(h3));
            }
        }
        #pragma unroll
        for(int k16=0;k16<4;++k16){
            uint32_t bvh[8][2], bvl[8][2];
            #pragma unroll
            for(int d16=0;d16<4;++d16){
                uint32_t off = swz((uint32_t)((k16*16+vrow_b)*128 + (d16*16+vcol_b)*2));
                uint32_t r[4];
                ldx4t(r, st+16384+off);
                bvh[d16*2][0]=r[0]; bvh[d16*2][1]=r[1]; bvh[d16*2+1][0]=r[2]; bvh[d16*2+1][1]=r[3];
                ldx4t(r, st+24576+off);
                bvl[d16*2][0]=r[0]; bvl[d16*2][1]=r[1]; bvl[d16*2+1][0]=r[2]; bvl[d16*2+1][1]=r[3];
            }
            #pragma unroll
            for(int t=0;t<8;++t){
                mma16816(O[t], ph[k16], bvh[t]);
                mma16816(O[t], ph[k16], bvl[t]);
                mma16816(O[t], pl[k16], bvh[t]);
            }
        }
        __syncthreads();
    }

    const int b = bh>>4, h = bh&15;
    #pragma unroll
    for(int rh=0; rh<2; ++rh){
        const float inv = 1.f/lstat[rh];
        const int row = q0 + wid*16 + rloc + rh*8;
        size_t base = (size_t)(b*TT+row)*DIM + h*64;
        #pragma unroll
        for(int t=0;t<8;++t){
            float v0 = O[t][rh*2]*inv, v1 = O[t][rh*2+1]*inv;
            size_t o = base + t*8 + cloc;
            bf16 h0=__float2bfloat16(v0), h1=__float2bfloat16(v1);
            g_y_hi[o]=h0; g_y_hi[o+1]=h1;
            g_y_lo[o]=__float2bfloat16(v0-__bfloat162float(h0));
            g_y_lo[o+1]=__float2bfloat16(v1-__bfloat162float(h1));
        }
    }
}

// ---------- router ----------
__global__ void router_kernel(const float* __restrict__ wr){
    const int n=blockIdx.x, tid=threadIdx.x;
    float acc[NEXP];
    #pragma unroll
    for(int e=0;e<NEXP;++e) acc[e]=0.f;
    const float* row=g_h2f+(size_t)n*DIM;
    for(int d=tid;d<DIM;d+=128){
        float hv=row[d];
        #pragma unroll
        for(int e=0;e<NEXP;++e) acc[e]+=hv*wr[d*NEXP+e];
    }
    __shared__ float sm[4][NEXP];
    #pragma unroll
    for(int e=0;e<NEXP;++e){
        float v=acc[e];
        #pragma unroll
        for(int o=16;o;o>>=1) v+=__shfl_xor_sync(~0u,v,o);
        if((tid&31)==0) sm[tid>>5][e]=v;
    }
    __syncthreads();
    if(tid==0){
        float lg[NEXP];
        #pragma unroll
        for(int e=0;e<NEXP;++e) lg[e]=sm[0][e]+sm[1][e]+sm[2][e]+sm[3][e];
        int e0=0;
        #pragma unroll
        for(int e=1;e<NEXP;++e) if(lg[e]>lg[e0]) e0=e;
        int e1=-1;
        #pragma unroll
        for(int e=0;e<NEXP;++e) if(e!=e0 && (e1<0||lg[e]>lg[e1])) e1=e;
        float w0=1.f/(1.f+__expf(lg[e1]-lg[e0])), w1=1.f-w0;
        int p0=atomicAdd(&g_cnt[e0],1);
        g_tok[e0*MAXTOK+p0]=n; g_wt[e0*MAXTOK+p0]=w0; g_slot[e0*MAXTOK+p0]=0;
        int p1=atomicAdd(&g_cnt[e1],1);
        g_tok[e1*MAXTOK+p1]=n; g_wt[e1*MAXTOK+p1]=w1; g_slot[e1*MAXTOK+p1]=1;
    }
}

// ---------- launch ----------
extern "C" void kernel_launch(void* const* d_in, const int* in_sizes, int n_in,
                              void* d_out, int out_size){
    const float* x      =(const float*)d_in[0];
    const float* ln1_g  =(const float*)d_in[1];
    const float* ln1_b  =(const float*)d_in[2];
    const float* w_attn =(const float*)d_in[3];
    const float* w_proj =(const float*)d_in[4];
    const float* ln2_g  =(const float*)d_in[5];
    const float* ln2_b  =(const float*)d_in[6];
    const float* w_rtr  =(const float*)d_in[7];
    const float* w1     =(const float*)d_in[8];
    const float* b1     =(const float*)d_in[9];
    const float* w2     =(const float*)d_in[10];
    const float* b2     =(const float*)d_in[11];
    float* out=(float*)d_out;

    const int SMG = 196608;
    cudaFuncSetAttribute(tgemm<0,3*DIM,DIM>, cudaFuncAttributeMaxDynamicSharedMemorySize, SMG);
    cudaFuncSetAttribute(tgemm<1,DIM,DIM>,   cudaFuncAttributeMaxDynamicSharedMemorySize, SMG);
    cudaFuncSetAttribute(tgemm<2,HID,DIM>,   cudaFuncAttributeMaxDynamicSharedMemorySize, SMG);
    cudaFuncSetAttribute(tgemm<3,DIM,HID>,   cudaFuncAttributeMaxDynamicSharedMemorySize, SMG);
    const int SMA = 131072;
    cudaFuncSetAttribute(attn_mma, cudaFuncAttributeMaxDynamicSharedMemorySize, SMA);

    zero_cnt_kernel<<<1,32>>>();
    transpose_split<0><<<dim3(96,32,1), dim3(32,8)>>>(w_attn);
    transpose_split<1><<<dim3(32,32,1), dim3(32,8)>>>(w_proj);
    transpose_split<2><<<dim3(128,32,NEXP), dim3(32,8)>>>(w1);
    transpose_split<3><<<dim3(32,128,NEXP), dim3(32,8)>>>(w2);

    ln_kernel<0><<<NTOK,256>>>(x, ln1_g, ln1_b);
    tgemm<0,3*DIM,DIM><<<dim3(12,32,1),256,SMG>>>(nullptr);
    attn_mma<<<dim3(TT/128, BB*16),256,SMA>>>();
    tgemm<1,DIM,DIM><<<dim3(4,32,1),256,SMG>>>(x);
    ln_kernel<1><<<NTOK,256>>>(nullptr, ln2_g, ln2_b);
    router_kernel<<<NTOK,128>>>(w_rtr);
    base_kernel<<<1,32>>>();
    tgemm<2,HID,DIM><<<dim3(16,32,NEXP),256,SMG>>>(b1);
    tgemm<3,DIM,HID><<<dim3(4,32,NEXP),256,SMG>>>(b2);
    final_kernel<<<NTOK*DIM/256,256>>>(out);
}